// round 1
// baseline (speedup 1.0000x reference)
#include <cuda_runtime.h>
#include <math.h>

// ---------------- problem constants ----------------
#define CC      128
#define NHEAD   4
#define HEADD   32
#define NTOK    392            // tokens per window
#define NWIN    128            // windows
#define MROWS   50176          // total tokens
#define HIDD    512
#define SCALE_Q 0.17677669529663687f   // 32^-0.5
#define SMEM_ATTN ((392*33*2 + 8*392*4 + 392)*4)

// ---------------- scratch (device globals; no allocation allowed) ----------------
__device__ float g_win[MROWS * CC];       // LN1+shift+partition output
__device__ float g_qkv[3 * MROWS * CC];   // (sel, win, head, n, d)
__device__ float g_y[MROWS * CC];         // attention output (win, n, c)
__device__ float g_x1[MROWS * CC];        // residual after proj
__device__ float g_m1[MROWS * CC];        // LN2 output
__device__ float g_hid[MROWS * HIDD];     // FC1 output

// ---------------- LN (+optional shift/window-partition) ----------------
// one warp per token row; 8 rows per 256-thread block
template<bool SHIFT>
__global__ void __launch_bounds__(256) ln_kernel(const float* __restrict__ x,
                                                 const float* __restrict__ gw,
                                                 const float* __restrict__ gb,
                                                 float* __restrict__ out) {
    int row  = blockIdx.x * 8 + (threadIdx.x >> 5);
    int lane = threadIdx.x & 31;
    int src;
    if (SHIFT) {
        int w = row / NTOK, n = row % NTOK;
        int dblk = w >> 6, hblk = (w >> 3) & 7, wblk = w & 7;
        int t = n / 49, hh = (n / 7) % 7, ww = n % 7;
        int gd = (dblk * 8 + t + 4) & 15;
        int gh = hblk * 7 + hh + 3; if (gh >= 56) gh -= 56;
        int gx = wblk * 7 + ww + 3; if (gx >= 56) gx -= 56;
        src = (gd * 56 + gh) * 56 + gx;
    } else {
        src = row;
    }
    float4 v = *(const float4*)(x + (size_t)src * CC + lane * 4);
    float s  = v.x + v.y + v.z + v.w;
    float ss = v.x*v.x + v.y*v.y + v.z*v.z + v.w*v.w;
    #pragma unroll
    for (int o = 16; o; o >>= 1) {
        s  += __shfl_xor_sync(~0u, s,  o);
        ss += __shfl_xor_sync(~0u, ss, o);
    }
    float mu  = s * (1.f / CC);
    float var = ss * (1.f / CC) - mu * mu;
    float rs  = rsqrtf(var + 1e-5f);
    float4 gwv = *(const float4*)(gw + lane * 4);
    float4 gbv = *(const float4*)(gb + lane * 4);
    float4 o4;
    o4.x = (v.x - mu) * rs * gwv.x + gbv.x;
    o4.y = (v.y - mu) * rs * gwv.y + gbv.y;
    o4.z = (v.z - mu) * rs * gwv.z + gbv.z;
    o4.w = (v.w - mu) * rs * gwv.w + gbv.w;
    *(float4*)(out + (size_t)row * CC + lane * 4) = o4;
}

// ---------------- 128x128x8 SGEMM, 8x8 microtile, fused epilogues ----------------
// out(M,ND) = A(M,KK) @ B(ND,KK)^T + bias, epilogue EPI:
//  0: QKV scatter (+scale q)   1: proj + window-reverse + residual(extra=x)
//  2: FC1 + exact GELU         3: FC2 + residual(extra=x1) -> out
template<int EPI, int ND, int KK>
__global__ void __launch_bounds__(256, 2) sgemm_kernel(const float* __restrict__ A,
                                                       const float* __restrict__ B,
                                                       const float* __restrict__ bias,
                                                       const float* __restrict__ extra,
                                                       float* __restrict__ out) {
    __shared__ float As[8][132];
    __shared__ float Bs[8][132];
    const int m0 = blockIdx.x * 128;
    const int n0 = blockIdx.y * 128;
    const int tid = threadIdx.x;
    const int tx = tid & 15, ty = tid >> 4;
    const int li = tid >> 1;            // load row within tile (0..127)
    const int lk = (tid & 1) * 4;       // load k offset (0 or 4)

    const float* Ap = A + (size_t)(m0 + li) * KK + lk;
    const float* Bp = B + (size_t)(n0 + li) * KK + lk;

    float acc[8][8];
    #pragma unroll
    for (int u = 0; u < 8; ++u)
        #pragma unroll
        for (int v = 0; v < 8; ++v) acc[u][v] = 0.f;

    float4 pa = *(const float4*)Ap;
    float4 pb = *(const float4*)Bp;

    const int steps = KK / 8;
    for (int kt = 0; kt < steps; ++kt) {
        As[lk+0][li] = pa.x; As[lk+1][li] = pa.y; As[lk+2][li] = pa.z; As[lk+3][li] = pa.w;
        Bs[lk+0][li] = pb.x; Bs[lk+1][li] = pb.y; Bs[lk+2][li] = pb.z; Bs[lk+3][li] = pb.w;
        __syncthreads();
        if (kt + 1 < steps) {
            pa = *(const float4*)(Ap + (kt + 1) * 8);
            pb = *(const float4*)(Bp + (kt + 1) * 8);
        }
        #pragma unroll
        for (int k = 0; k < 8; ++k) {
            float4 a0 = *(const float4*)&As[k][ty * 8];
            float4 a1 = *(const float4*)&As[k][ty * 8 + 4];
            float4 b0 = *(const float4*)&Bs[k][tx * 8];
            float4 b1 = *(const float4*)&Bs[k][tx * 8 + 4];
            float a[8] = {a0.x,a0.y,a0.z,a0.w,a1.x,a1.y,a1.z,a1.w};
            float b[8] = {b0.x,b0.y,b0.z,b0.w,b1.x,b1.y,b1.z,b1.w};
            #pragma unroll
            for (int u = 0; u < 8; ++u)
                #pragma unroll
                for (int v = 0; v < 8; ++v) acc[u][v] += a[u] * b[v];
        }
        __syncthreads();
    }

    // epilogue
    #pragma unroll
    for (int u = 0; u < 8; ++u) {
        int m = m0 + ty * 8 + u;
        if (EPI == 0) {                 // QKV scatter
            int w = m / NTOK, n = m % NTOK;
            #pragma unroll
            for (int v = 0; v < 8; ++v) {
                int j = n0 + tx * 8 + v;
                float val = acc[u][v] + bias[j];
                int sel = j >> 7, hd = (j >> 5) & 3, dch = j & 31;
                if (sel == 0) val *= SCALE_Q;
                out[(size_t)(((sel * NWIN + w) * NHEAD + hd) * NTOK + n) * HEADD + dch] = val;
            }
        } else if (EPI == 1) {          // proj + window reverse + shift + residual
            int w = m / NTOK, n = m % NTOK;
            int dblk = w >> 6, hblk = (w >> 3) & 7, wblk = w & 7;
            int t = n / 49, hh = (n / 7) % 7, ww = n % 7;
            int gd = (dblk * 8 + t + 4) & 15;
            int gh = hblk * 7 + hh + 3; if (gh >= 56) gh -= 56;
            int gx = wblk * 7 + ww + 3; if (gx >= 56) gx -= 56;
            size_t lin = ((size_t)(gd * 56 + gh) * 56 + gx) * CC;
            #pragma unroll
            for (int v = 0; v < 8; ++v) {
                int j = n0 + tx * 8 + v;
                out[lin + j] = extra[lin + j] + acc[u][v] + bias[j];
            }
        } else if (EPI == 2) {          // FC1 + exact GELU
            #pragma unroll
            for (int v = 0; v < 8; ++v) {
                int j = n0 + tx * 8 + v;
                float val = acc[u][v] + bias[j];
                out[(size_t)m * HIDD + j] = 0.5f * val * (1.f + erff(val * 0.70710678118654752f));
            }
        } else {                        // FC2 + residual -> final output
            #pragma unroll
            for (int v = 0; v < 8; ++v) {
                int j = n0 + tx * 8 + v;
                out[(size_t)m * CC + j] = acc[u][v] + bias[j] + extra[(size_t)m * CC + j];
            }
        }
    }
}

// ---------------- fused windowed attention: one block per (window, head) ----------------
__global__ void __launch_bounds__(256) attn_kernel(const float* __restrict__ qkv,
                                                   const float* __restrict__ relt,
                                                   float* __restrict__ y) {
    const int w    = blockIdx.x >> 2;
    const int head = blockIdx.x & 3;
    extern __shared__ float sm[];
    float* Ks    = sm;                       // [392][33]
    float* Vs    = sm + NTOK * 33;           // [392][33]
    float* pbAll = Vs + NTOK * 33;           // [8][392][4]
    int*   cinfo = (int*)(pbAll + 8 * NTOK * 4);

    const int tid = threadIdx.x, lane = tid & 31, wid = tid >> 5;
    const size_t hw = ((size_t)w * NHEAD + head) * NTOK * HEADD;
    const float* qb = qkv + hw;
    const float* kb = qkv + (size_t)MROWS * CC + hw;
    const float* vb = qkv + 2 * (size_t)MROWS * CC + hw;

    // stage K,V into padded smem
    for (int i = tid; i < NTOK * 8; i += 256) {
        int m = i >> 3, c4 = (i & 7) << 2;
        float4 kk = *(const float4*)(kb + m * 32 + c4);
        float4 vv = *(const float4*)(vb + m * 32 + c4);
        float* kd = Ks + m * 33 + c4;
        kd[0] = kk.x; kd[1] = kk.y; kd[2] = kk.z; kd[3] = kk.w;
        float* vd = Vs + m * 33 + c4;
        vd[0] = vv.x; vd[1] = vv.y; vd[2] = vv.z; vd[3] = vv.w;
    }
    // packed token coords + shift-mask region
    const int dblk = w >> 6, hblk = (w >> 3) & 7, wblk = w & 7;
    for (int m = tid; m < NTOK; m += 256) {
        int t = m / 49, hh = (m / 7) % 7, ww = m % 7;
        int gd = dblk * 8 + t, gh = hblk * 7 + hh, gx = wblk * 7 + ww;
        int rd = (gd < 8)  ? 0 : ((gd < 12) ? 1 : 2);
        int rh = (gh < 49) ? 0 : ((gh < 53) ? 1 : 2);
        int rw = (gx < 49) ? 0 : ((gx < 53) ? 1 : 2);
        cinfo[m] = t | (hh << 4) | (ww << 8) | ((rd * 9 + rh * 3 + rw) << 12);
    }
    __syncthreads();

    float* pbw = pbAll + wid * NTOK * 4;

    // each warp: query-row quads (n0, n0+98, n0+196, n0+294)
    for (int n0 = wid; n0 < 98; n0 += 8) {
        float q[4][32];
        int ci[4];
        #pragma unroll
        for (int r = 0; r < 4; ++r) {
            int n = n0 + r * 98;
            const float4* qr = (const float4*)(qb + n * 32);
            #pragma unroll
            for (int c4 = 0; c4 < 8; ++c4) {
                float4 qv = qr[c4];
                q[r][c4*4+0] = qv.x; q[r][c4*4+1] = qv.y;
                q[r][c4*4+2] = qv.z; q[r][c4*4+3] = qv.w;
            }
            ci[r] = cinfo[n];
        }
        __syncwarp();
        float s0 = 0.f, s1 = 0.f, s2 = 0.f, s3 = 0.f;
        #pragma unroll 2
        for (int j = 0; j < 13; ++j) {
            int m = lane + 32 * j;
            if (m < NTOK) {
                float a0 = 0.f, a1 = 0.f, a2 = 0.f, a3 = 0.f;
                #pragma unroll
                for (int c = 0; c < 32; ++c) {
                    float kv = Ks[m * 33 + c];
                    a0 += q[0][c] * kv; a1 += q[1][c] * kv;
                    a2 += q[2][c] * kv; a3 += q[3][c] * kv;
                }
                int cm = cinfo[m];
                int mt = cm & 15, mh = (cm >> 4) & 15, mw = (cm >> 8) & 15, mr = cm >> 12;
                float bb[4];
                #pragma unroll
                for (int r = 0; r < 4; ++r) {
                    int c2 = ci[r];
                    int idx = (((c2 & 15) - mt + 7) * 169)
                            + ((((c2 >> 4) & 15) - mh + 6) * 13)
                            + (((c2 >> 8) & 15) - mw + 6);
                    float bias = __ldg(relt + idx * NHEAD + head);
                    bb[r] = bias + (((c2 >> 12) == mr) ? 0.f : -100.f);
                }
                // logits are O(1) here; mask -100 underflows exp to exactly 0,
                // so max-free softmax is rounding-identical
                float e0 = __expf(a0 + bb[0]);
                float e1 = __expf(a1 + bb[1]);
                float e2 = __expf(a2 + bb[2]);
                float e3 = __expf(a3 + bb[3]);
                *(float4*)(pbw + m * 4) = make_float4(e0, e1, e2, e3);
                s0 += e0; s1 += e1; s2 += e2; s3 += e3;
            }
        }
        #pragma unroll
        for (int o = 16; o; o >>= 1) {
            s0 += __shfl_xor_sync(~0u, s0, o);
            s1 += __shfl_xor_sync(~0u, s1, o);
            s2 += __shfl_xor_sync(~0u, s2, o);
            s3 += __shfl_xor_sync(~0u, s3, o);
        }
        float r0 = 1.f / s0, r1 = 1.f / s1, r2 = 1.f / s2, r3 = 1.f / s3;
        __syncwarp();
        // P @ V: lane owns channel c=lane
        float o0 = 0.f, o1 = 0.f, o2 = 0.f, o3 = 0.f;
        #pragma unroll 4
        for (int m = 0; m < NTOK; ++m) {
            float4 p = *(const float4*)(pbw + m * 4);
            float vv = Vs[m * 33 + lane];
            o0 += p.x * vv; o1 += p.y * vv; o2 += p.z * vv; o3 += p.w * vv;
        }
        size_t yb = ((size_t)w * NTOK) * CC + head * HEADD + lane;
        y[yb + (size_t)(n0      ) * CC] = o0 * r0;
        y[yb + (size_t)(n0 +  98) * CC] = o1 * r1;
        y[yb + (size_t)(n0 + 196) * CC] = o2 * r2;
        y[yb + (size_t)(n0 + 294) * CC] = o3 * r3;
        __syncwarp();
    }
}

// ---------------- launch ----------------
extern "C" void kernel_launch(void* const* d_in, const int* in_sizes, int n_in,
                              void* d_out, int out_size) {
    (void)in_sizes; (void)n_in; (void)out_size;
    const float* x     = (const float*)d_in[0];
    const float* n1w   = (const float*)d_in[1];
    const float* n1b   = (const float*)d_in[2];
    const float* qkvw  = (const float*)d_in[3];
    const float* qkvb  = (const float*)d_in[4];
    const float* relt  = (const float*)d_in[5];
    const float* projw = (const float*)d_in[6];
    const float* projb = (const float*)d_in[7];
    const float* n2w   = (const float*)d_in[8];
    const float* n2b   = (const float*)d_in[9];
    const float* fc1w  = (const float*)d_in[10];
    const float* fc1b  = (const float*)d_in[11];
    const float* fc2w  = (const float*)d_in[12];
    const float* fc2b  = (const float*)d_in[13];

    float *win, *qkvB, *yB, *x1, *m1, *hid;
    cudaGetSymbolAddress((void**)&win,  g_win);
    cudaGetSymbolAddress((void**)&qkvB, g_qkv);
    cudaGetSymbolAddress((void**)&yB,   g_y);
    cudaGetSymbolAddress((void**)&x1,   g_x1);
    cudaGetSymbolAddress((void**)&m1,   g_m1);
    cudaGetSymbolAddress((void**)&hid,  g_hid);

    cudaFuncSetAttribute(attn_kernel, cudaFuncAttributeMaxDynamicSharedMemorySize, SMEM_ATTN);

    ln_kernel<true><<<MROWS / 8, 256>>>(x, n1w, n1b, win);
    sgemm_kernel<0, 384, 128><<<dim3(392, 3), 256>>>(win, qkvw, qkvb, nullptr, qkvB);
    attn_kernel<<<NWIN * NHEAD, 256, SMEM_ATTN>>>(qkvB, relt, yB);
    sgemm_kernel<1, 128, 128><<<dim3(392, 1), 256>>>(yB, projw, projb, x, x1);
    ln_kernel<false><<<MROWS / 8, 256>>>(x1, n2w, n2b, m1);
    sgemm_kernel<2, 512, 128><<<dim3(392, 4), 256>>>(m1, fc1w, fc1b, nullptr, hid);
    sgemm_kernel<3, 128, 512><<<dim3(392, 1), 256>>>(hid, fc2w, fc2b, x1, (float*)d_out);
}

// round 2
// speedup vs baseline: 1.7310x; 1.7310x over previous
#include <cuda_runtime.h>
#include <cuda_bf16.h>
#include <math.h>
#include <stdint.h>

// ---------------- problem constants ----------------
#define CC      128
#define NHEAD   4
#define HEADD   32
#define NTOK    392
#define NWIN    128
#define MROWS   50176
#define HIDD    512
#define SCALE_Q 0.17677669529663687f
#define SMEM_ATTN ((392*33*2 + 8*392*4 + 392)*4)
#define SMEM_GEMM 65536

typedef __nv_bfloat16 bf16;

// ---------------- scratch (device globals) ----------------
__device__ __align__(16) bf16  g_win[MROWS * CC];      // LN1+shift+partition (bf16)
__device__ __align__(16) float g_qkv[3 * MROWS * CC];  // (sel, win, head, n, d) fp32
__device__ __align__(16) bf16  g_y[MROWS * CC];        // attention out (win,n,c) bf16
__device__ __align__(16) float g_x1[MROWS * CC];       // residual after proj
__device__ __align__(16) bf16  g_m1[MROWS * CC];       // LN2 out bf16
__device__ __align__(16) bf16  g_hid[MROWS * HIDD];    // FC1+GELU out bf16
__device__ __align__(16) bf16  g_wb[196608];           // bf16 weights: qkv|proj|fc1|fc2

// ---------------- weight fp32 -> bf16 ----------------
__global__ void cvt_kernel(const float* __restrict__ s, bf16* __restrict__ d, int n4) {
    int i = blockIdx.x * 256 + threadIdx.x;
    if (i < n4) {
        float4 v = ((const float4*)s)[i];
        __nv_bfloat162 p0 = __floats2bfloat162_rn(v.x, v.y);
        __nv_bfloat162 p1 = __floats2bfloat162_rn(v.z, v.w);
        ((uint2*)d)[i] = make_uint2(*(uint32_t*)&p0, *(uint32_t*)&p1);
    }
}

// ---------------- LN (+optional shift/window-partition), bf16 out ----------------
template<bool SHIFT>
__global__ void __launch_bounds__(256) ln_kernel(const float* __restrict__ x,
                                                 const float* __restrict__ gw,
                                                 const float* __restrict__ gb,
                                                 bf16* __restrict__ out) {
    int row  = blockIdx.x * 8 + (threadIdx.x >> 5);
    int lane = threadIdx.x & 31;
    int src;
    if (SHIFT) {
        int w = row / NTOK, n = row % NTOK;
        int dblk = w >> 6, hblk = (w >> 3) & 7, wblk = w & 7;
        int t = n / 49, hh = (n / 7) % 7, ww = n % 7;
        int gd = (dblk * 8 + t + 4) & 15;
        int gh = hblk * 7 + hh + 3; if (gh >= 56) gh -= 56;
        int gx = wblk * 7 + ww + 3; if (gx >= 56) gx -= 56;
        src = (gd * 56 + gh) * 56 + gx;
    } else {
        src = row;
    }
    float4 v = *(const float4*)(x + (size_t)src * CC + lane * 4);
    float s  = v.x + v.y + v.z + v.w;
    float ss = v.x*v.x + v.y*v.y + v.z*v.z + v.w*v.w;
    #pragma unroll
    for (int o = 16; o; o >>= 1) {
        s  += __shfl_xor_sync(~0u, s,  o);
        ss += __shfl_xor_sync(~0u, ss, o);
    }
    float mu  = s * (1.f / CC);
    float var = ss * (1.f / CC) - mu * mu;
    float rs  = rsqrtf(var + 1e-5f);
    float4 gwv = *(const float4*)(gw + lane * 4);
    float4 gbv = *(const float4*)(gb + lane * 4);
    float o0 = (v.x - mu) * rs * gwv.x + gbv.x;
    float o1 = (v.y - mu) * rs * gwv.y + gbv.y;
    float o2 = (v.z - mu) * rs * gwv.z + gbv.z;
    float o3 = (v.w - mu) * rs * gwv.w + gbv.w;
    __nv_bfloat162 p0 = __floats2bfloat162_rn(o0, o1);
    __nv_bfloat162 p1 = __floats2bfloat162_rn(o2, o3);
    *(uint2*)(out + (size_t)row * CC + lane * 4) = make_uint2(*(uint32_t*)&p0, *(uint32_t*)&p1);
}

// ---------------- bf16 tensor-core GEMM (mma.sync m16n8k16) ----------------
// out(M,ND) = A(M,KK) @ B(ND,KK)^T + bias, fused epilogue EPI as in round 0.
__device__ __forceinline__ void cp16(uint32_t dst, const void* src) {
    asm volatile("cp.async.cg.shared.global [%0], [%1], 16;\n" :: "r"(dst), "l"(src));
}
__device__ __forceinline__ uint32_t swz(int row, int kb) {
    return (uint32_t)((row << 7) + (kb ^ ((row & 7) << 4)));
}

template<int EPI, int ND, int KK>
__global__ void __launch_bounds__(256) mgemm(const bf16* __restrict__ A,
                                             const bf16* __restrict__ B,
                                             const float* __restrict__ bias,
                                             const float* __restrict__ extra,
                                             void* __restrict__ outv) {
    extern __shared__ char smc[];
    const uint32_t smb = (uint32_t)__cvta_generic_to_shared(smc);
    const int tid = threadIdx.x, lane = tid & 31, warp = tid >> 5;
    const int wm = warp >> 2, wn = warp & 3;
    const int m0 = blockIdx.x * 128, n0 = blockIdx.y * 128;
    constexpr int NK = KK / 64;

    float c[4][4][4];
    #pragma unroll
    for (int a = 0; a < 4; ++a)
        #pragma unroll
        for (int b = 0; b < 4; ++b)
            #pragma unroll
            for (int e = 0; e < 4; ++e) c[a][b][e] = 0.f;

    auto load = [&](int kt, int st) {
        uint32_t ab = smb + st * 32768;
        uint32_t bb = ab + 16384;
        #pragma unroll
        for (int i = 0; i < 4; ++i) {
            int cid = tid + i * 256;
            int row = cid >> 3, kb = (cid & 7) * 16;
            cp16(ab + swz(row, kb), (const char*)(A + (size_t)(m0 + row) * KK + kt * 64) + kb);
            cp16(bb + swz(row, kb), (const char*)(B + (size_t)(n0 + row) * KK + kt * 64) + kb);
        }
        asm volatile("cp.async.commit_group;\n");
    };

    load(0, 0);
    for (int kt = 0; kt < NK; ++kt) {
        if (kt + 1 < NK) {
            load(kt + 1, (kt + 1) & 1);
            asm volatile("cp.async.wait_group 1;\n");
        } else {
            asm volatile("cp.async.wait_group 0;\n");
        }
        __syncthreads();
        uint32_t ab = smb + (kt & 1) * 32768, bb = ab + 16384;
        #pragma unroll
        for (int ks = 0; ks < 4; ++ks) {
            uint32_t af[4][4], bfr[4][2];
            #pragma unroll
            for (int mi = 0; mi < 4; ++mi) {
                int row = wm * 64 + mi * 16 + (lane & 15);
                int kb  = ks * 32 + ((lane & 16) ? 16 : 0);
                uint32_t ad = ab + swz(row, kb);
                asm volatile("ldmatrix.sync.aligned.m8n8.x4.shared.b16 {%0,%1,%2,%3}, [%4];\n"
                    : "=r"(af[mi][0]), "=r"(af[mi][1]), "=r"(af[mi][2]), "=r"(af[mi][3])
                    : "r"(ad));
            }
            #pragma unroll
            for (int p = 0; p < 2; ++p) {
                int row = wn * 32 + p * 16 + (lane & 7) + ((lane & 16) ? 8 : 0);
                int kb  = ks * 32 + ((lane & 8) ? 16 : 0);
                uint32_t bd = bb + swz(row, kb);
                asm volatile("ldmatrix.sync.aligned.m8n8.x4.shared.b16 {%0,%1,%2,%3}, [%4];\n"
                    : "=r"(bfr[p*2][0]), "=r"(bfr[p*2][1]), "=r"(bfr[p*2+1][0]), "=r"(bfr[p*2+1][1])
                    : "r"(bd));
            }
            #pragma unroll
            for (int mi = 0; mi < 4; ++mi)
                #pragma unroll
                for (int ni = 0; ni < 4; ++ni)
                    asm volatile("mma.sync.aligned.m16n8k16.row.col.f32.bf16.bf16.f32 "
                        "{%0,%1,%2,%3}, {%4,%5,%6,%7}, {%8,%9}, {%0,%1,%2,%3};\n"
                        : "+f"(c[mi][ni][0]), "+f"(c[mi][ni][1]), "+f"(c[mi][ni][2]), "+f"(c[mi][ni][3])
                        : "r"(af[mi][0]), "r"(af[mi][1]), "r"(af[mi][2]), "r"(af[mi][3]),
                          "r"(bfr[ni][0]), "r"(bfr[ni][1]));
        }
        __syncthreads();
    }

    // ---------------- epilogue ----------------
    const int colb = n0 + wn * 32 + (lane & 3) * 2;
    #pragma unroll
    for (int mi = 0; mi < 4; ++mi) {
        #pragma unroll
        for (int h = 0; h < 2; ++h) {
            int m = m0 + wm * 64 + mi * 16 + (lane >> 2) + h * 8;
            if (EPI == 0) {                 // QKV scatter (+scale q)
                int w = m / NTOK, n = m % NTOK;
                float* out = (float*)outv;
                #pragma unroll
                for (int ni = 0; ni < 4; ++ni) {
                    int j = colb + ni * 8;
                    float v0 = c[mi][ni][h*2+0] + bias[j];
                    float v1 = c[mi][ni][h*2+1] + bias[j+1];
                    int sel = j >> 7, hd = (j >> 5) & 3, dch = j & 31;
                    if (sel == 0) { v0 *= SCALE_Q; v1 *= SCALE_Q; }
                    *(float2*)(out + (size_t)(((sel*NWIN + w)*NHEAD + hd)*NTOK + n)*HEADD + dch)
                        = make_float2(v0, v1);
                }
            } else if (EPI == 1) {          // proj + window-reverse + shift + residual
                int w = m / NTOK, n = m % NTOK;
                int dblk = w >> 6, hblk = (w >> 3) & 7, wblk = w & 7;
                int t = n / 49, hh = (n / 7) % 7, ww = n % 7;
                int gd = (dblk * 8 + t + 4) & 15;
                int gh = hblk * 7 + hh + 3; if (gh >= 56) gh -= 56;
                int gx = wblk * 7 + ww + 3; if (gx >= 56) gx -= 56;
                size_t lin = ((size_t)(gd * 56 + gh) * 56 + gx) * CC;
                float* out = (float*)outv;
                #pragma unroll
                for (int ni = 0; ni < 4; ++ni) {
                    int j = colb + ni * 8;
                    float2 e = *(const float2*)(extra + lin + j);
                    *(float2*)(out + lin + j) = make_float2(
                        c[mi][ni][h*2+0] + bias[j]   + e.x,
                        c[mi][ni][h*2+1] + bias[j+1] + e.y);
                }
            } else if (EPI == 2) {          // FC1 + exact GELU -> bf16
                bf16* out = (bf16*)outv;
                #pragma unroll
                for (int ni = 0; ni < 4; ++ni) {
                    int j = colb + ni * 8;
                    float v0 = c[mi][ni][h*2+0] + bias[j];
                    float v1 = c[mi][ni][h*2+1] + bias[j+1];
                    v0 = 0.5f * v0 * (1.f + erff(v0 * 0.70710678118654752f));
                    v1 = 0.5f * v1 * (1.f + erff(v1 * 0.70710678118654752f));
                    __nv_bfloat162 p = __floats2bfloat162_rn(v0, v1);
                    *(uint32_t*)(out + (size_t)m * HIDD + j) = *(uint32_t*)&p;
                }
            } else {                        // FC2 + residual -> final fp32 out
                float* out = (float*)outv;
                #pragma unroll
                for (int ni = 0; ni < 4; ++ni) {
                    int j = colb + ni * 8;
                    float2 e = *(const float2*)(extra + (size_t)m * CC + j);
                    *(float2*)(out + (size_t)m * CC + j) = make_float2(
                        c[mi][ni][h*2+0] + bias[j]   + e.x,
                        c[mi][ni][h*2+1] + bias[j+1] + e.y);
                }
            }
        }
    }
}

// ---------------- fused windowed attention (fp32), bf16 output ----------------
__global__ void __launch_bounds__(256) attn_kernel(const float* __restrict__ qkv,
                                                   const float* __restrict__ relt,
                                                   bf16* __restrict__ y) {
    const int w    = blockIdx.x >> 2;
    const int head = blockIdx.x & 3;
    extern __shared__ float sm[];
    float* Ks    = sm;                       // [392][33]
    float* Vs    = sm + NTOK * 33;           // [392][33]
    float* pbAll = Vs + NTOK * 33;           // [8][392][4]
    int*   cinfo = (int*)(pbAll + 8 * NTOK * 4);

    const int tid = threadIdx.x, lane = tid & 31, wid = tid >> 5;
    const size_t hw = ((size_t)w * NHEAD + head) * NTOK * HEADD;
    const float* qb = qkv + hw;
    const float* kb = qkv + (size_t)MROWS * CC + hw;
    const float* vb = qkv + 2 * (size_t)MROWS * CC + hw;

    for (int i = tid; i < NTOK * 8; i += 256) {
        int m = i >> 3, c4 = (i & 7) << 2;
        float4 kk = *(const float4*)(kb + m * 32 + c4);
        float4 vv = *(const float4*)(vb + m * 32 + c4);
        float* kd = Ks + m * 33 + c4;
        kd[0] = kk.x; kd[1] = kk.y; kd[2] = kk.z; kd[3] = kk.w;
        float* vd = Vs + m * 33 + c4;
        vd[0] = vv.x; vd[1] = vv.y; vd[2] = vv.z; vd[3] = vv.w;
    }
    const int dblk = w >> 6, hblk = (w >> 3) & 7, wblk = w & 7;
    for (int m = tid; m < NTOK; m += 256) {
        int t = m / 49, hh = (m / 7) % 7, ww = m % 7;
        int gd = dblk * 8 + t, gh = hblk * 7 + hh, gx = wblk * 7 + ww;
        int rd = (gd < 8)  ? 0 : ((gd < 12) ? 1 : 2);
        int rh = (gh < 49) ? 0 : ((gh < 53) ? 1 : 2);
        int rw = (gx < 49) ? 0 : ((gx < 53) ? 1 : 2);
        cinfo[m] = t | (hh << 4) | (ww << 8) | ((rd * 9 + rh * 3 + rw) << 12);
    }
    __syncthreads();

    float* pbw = pbAll + wid * NTOK * 4;

    for (int n0 = wid; n0 < 98; n0 += 8) {
        float q[4][32];
        int ci[4];
        #pragma unroll
        for (int r = 0; r < 4; ++r) {
            int n = n0 + r * 98;
            const float4* qr = (const float4*)(qb + n * 32);
            #pragma unroll
            for (int c4 = 0; c4 < 8; ++c4) {
                float4 qv = qr[c4];
                q[r][c4*4+0] = qv.x; q[r][c4*4+1] = qv.y;
                q[r][c4*4+2] = qv.z; q[r][c4*4+3] = qv.w;
            }
            ci[r] = cinfo[n];
        }
        __syncwarp();
        float s0 = 0.f, s1 = 0.f, s2 = 0.f, s3 = 0.f;
        #pragma unroll 2
        for (int j = 0; j < 13; ++j) {
            int m = lane + 32 * j;
            if (m < NTOK) {
                float a0 = 0.f, a1 = 0.f, a2 = 0.f, a3 = 0.f;
                #pragma unroll
                for (int cix = 0; cix < 32; ++cix) {
                    float kv = Ks[m * 33 + cix];
                    a0 += q[0][cix] * kv; a1 += q[1][cix] * kv;
                    a2 += q[2][cix] * kv; a3 += q[3][cix] * kv;
                }
                int cm = cinfo[m];
                int mt = cm & 15, mh = (cm >> 4) & 15, mw = (cm >> 8) & 15, mr = cm >> 12;
                float bb[4];
                #pragma unroll
                for (int r = 0; r < 4; ++r) {
                    int c2 = ci[r];
                    int idx = (((c2 & 15) - mt + 7) * 169)
                            + ((((c2 >> 4) & 15) - mh + 6) * 13)
                            + (((c2 >> 8) & 15) - mw + 6);
                    float bias = __ldg(relt + idx * NHEAD + head);
                    bb[r] = bias + (((c2 >> 12) == mr) ? 0.f : -100.f);
                }
                float e0 = __expf(a0 + bb[0]);
                float e1 = __expf(a1 + bb[1]);
                float e2 = __expf(a2 + bb[2]);
                float e3 = __expf(a3 + bb[3]);
                *(float4*)(pbw + m * 4) = make_float4(e0, e1, e2, e3);
                s0 += e0; s1 += e1; s2 += e2; s3 += e3;
            }
        }
        #pragma unroll
        for (int o = 16; o; o >>= 1) {
            s0 += __shfl_xor_sync(~0u, s0, o);
            s1 += __shfl_xor_sync(~0u, s1, o);
            s2 += __shfl_xor_sync(~0u, s2, o);
            s3 += __shfl_xor_sync(~0u, s3, o);
        }
        float r0 = 1.f / s0, r1 = 1.f / s1, r2 = 1.f / s2, r3 = 1.f / s3;
        __syncwarp();
        float o0 = 0.f, o1 = 0.f, o2 = 0.f, o3 = 0.f;
        #pragma unroll 4
        for (int m = 0; m < NTOK; ++m) {
            float4 p = *(const float4*)(pbw + m * 4);
            float vv = Vs[m * 33 + lane];
            o0 += p.x * vv; o1 += p.y * vv; o2 += p.z * vv; o3 += p.w * vv;
        }
        size_t yb = ((size_t)w * NTOK) * CC + head * HEADD + lane;
        y[yb + (size_t)(n0      ) * CC] = __float2bfloat16(o0 * r0);
        y[yb + (size_t)(n0 +  98) * CC] = __float2bfloat16(o1 * r1);
        y[yb + (size_t)(n0 + 196) * CC] = __float2bfloat16(o2 * r2);
        y[yb + (size_t)(n0 + 294) * CC] = __float2bfloat16(o3 * r3);
        __syncwarp();
    }
}

// ---------------- launch ----------------
extern "C" void kernel_launch(void* const* d_in, const int* in_sizes, int n_in,
                              void* d_out, int out_size) {
    (void)in_sizes; (void)n_in; (void)out_size;
    const float* x     = (const float*)d_in[0];
    const float* n1w   = (const float*)d_in[1];
    const float* n1b   = (const float*)d_in[2];
    const float* qkvw  = (const float*)d_in[3];
    const float* qkvb  = (const float*)d_in[4];
    const float* relt  = (const float*)d_in[5];
    const float* projw = (const float*)d_in[6];
    const float* projb = (const float*)d_in[7];
    const float* n2w   = (const float*)d_in[8];
    const float* n2b   = (const float*)d_in[9];
    const float* fc1w  = (const float*)d_in[10];
    const float* fc1b  = (const float*)d_in[11];
    const float* fc2w  = (const float*)d_in[12];
    const float* fc2b  = (const float*)d_in[13];

    bf16 *win, *yB, *m1, *hid, *wb;
    float *qkvB, *x1;
    cudaGetSymbolAddress((void**)&win,  g_win);
    cudaGetSymbolAddress((void**)&qkvB, g_qkv);
    cudaGetSymbolAddress((void**)&yB,   g_y);
    cudaGetSymbolAddress((void**)&x1,   g_x1);
    cudaGetSymbolAddress((void**)&m1,   g_m1);
    cudaGetSymbolAddress((void**)&hid,  g_hid);
    cudaGetSymbolAddress((void**)&wb,   g_wb);

    cudaFuncSetAttribute(attn_kernel, cudaFuncAttributeMaxDynamicSharedMemorySize, SMEM_ATTN);
    cudaFuncSetAttribute(mgemm<0,384,128>, cudaFuncAttributeMaxDynamicSharedMemorySize, SMEM_GEMM);
    cudaFuncSetAttribute(mgemm<1,128,128>, cudaFuncAttributeMaxDynamicSharedMemorySize, SMEM_GEMM);
    cudaFuncSetAttribute(mgemm<2,512,128>, cudaFuncAttributeMaxDynamicSharedMemorySize, SMEM_GEMM);
    cudaFuncSetAttribute(mgemm<3,128,512>, cudaFuncAttributeMaxDynamicSharedMemorySize, SMEM_GEMM);

    // weight conversion (bf16): qkv @0, proj @49152, fc1 @65536, fc2 @131072
    cvt_kernel<<<48, 256>>>(qkvw,  wb,          12288);
    cvt_kernel<<<16, 256>>>(projw, wb + 49152,  4096);
    cvt_kernel<<<64, 256>>>(fc1w,  wb + 65536,  16384);
    cvt_kernel<<<64, 256>>>(fc2w,  wb + 131072, 16384);

    ln_kernel<true><<<MROWS / 8, 256>>>(x, n1w, n1b, win);
    mgemm<0, 384, 128><<<dim3(392, 3), 256, SMEM_GEMM>>>(win, wb, qkvb, nullptr, qkvB);
    attn_kernel<<<NWIN * NHEAD, 256, SMEM_ATTN>>>(qkvB, relt, yB);
    mgemm<1, 128, 128><<<dim3(392, 1), 256, SMEM_GEMM>>>(yB, wb + 49152, projb, x, x1);
    ln_kernel<false><<<MROWS / 8, 256>>>(x1, n2w, n2b, m1);
    mgemm<2, 512, 128><<<dim3(392, 4), 256, SMEM_GEMM>>>(m1, wb + 65536, fc1b, nullptr, hid);
    mgemm<3, 128, 512><<<dim3(392, 1), 256, SMEM_GEMM>>>(hid, wb + 131072, fc2b, x1, (float*)d_out);
}

// round 3
// speedup vs baseline: 4.2598x; 2.4609x over previous
#include <cuda_runtime.h>
#include <cuda_bf16.h>
#include <math.h>
#include <stdint.h>

// ---------------- problem constants ----------------
#define CC      128
#define NHEAD   4
#define HEADD   32
#define NTOK    392
#define NPAD    400
#define NWIN    128
#define MROWS   50176
#define HIDD    512
#define SCALE_Q 0.17677669529663687f
#define SMEM_GEMM 65536
#define SMEM_ATT  64000     // Ks + Vs, 400 rows x 80B each

typedef __nv_bfloat16 bf16;

// ---------------- scratch (device globals) ----------------
__device__ __align__(16) bf16  g_win[MROWS * CC];
__device__ __align__(16) bf16  g_qkv[3 * MROWS * CC];   // bf16 (sel,w,head,n,d)
__device__ __align__(16) bf16  g_y[MROWS * CC];
__device__ __align__(16) float g_x1[MROWS * CC];
__device__ __align__(16) bf16  g_m1[MROWS * CC];
__device__ __align__(16) bf16  g_hid[MROWS * HIDD];
__device__ __align__(16) bf16  g_wb[196608];
__device__ __align__(16) bf16  g_btab[8 * NHEAD * NPAD * NPAD]; // bias+mask table

// ---------------- asm helpers ----------------
__device__ __forceinline__ void cp16(uint32_t dst, const void* src) {
    asm volatile("cp.async.cg.shared.global [%0], [%1], 16;\n" :: "r"(dst), "l"(src));
}
__device__ __forceinline__ uint32_t swz(int row, int kb) {
    return (uint32_t)((row << 7) + (kb ^ ((row & 7) << 4)));
}
#define LDSM4(R, addr) \
    asm volatile("ldmatrix.sync.aligned.m8n8.x4.shared.b16 {%0,%1,%2,%3}, [%4];\n" \
        : "=r"((R)[0]), "=r"((R)[1]), "=r"((R)[2]), "=r"((R)[3]) : "r"(addr))
#define LDSM4T(R, addr) \
    asm volatile("ldmatrix.sync.aligned.m8n8.x4.trans.shared.b16 {%0,%1,%2,%3}, [%4];\n" \
        : "=r"((R)[0]), "=r"((R)[1]), "=r"((R)[2]), "=r"((R)[3]) : "r"(addr))
#define MMA16816(d, a0,a1,a2,a3, b0,b1) \
    asm volatile("mma.sync.aligned.m16n8k16.row.col.f32.bf16.bf16.f32 " \
        "{%0,%1,%2,%3}, {%4,%5,%6,%7}, {%8,%9}, {%0,%1,%2,%3};\n" \
        : "+f"((d)[0]), "+f"((d)[1]), "+f"((d)[2]), "+f"((d)[3]) \
        : "r"(a0), "r"(a1), "r"(a2), "r"(a3), "r"(b0), "r"(b1))

__device__ __forceinline__ uint32_t packbf(float a, float b) {
    __nv_bfloat162 p = __floats2bfloat162_rn(a, b);
    return *(uint32_t*)&p;
}
__device__ __forceinline__ float2 unpackbf(uint32_t u) {
    return __bfloat1622float2(*(__nv_bfloat162*)&u);
}

// ---------------- weight fp32 -> bf16 ----------------
__global__ void cvt_kernel(const float* __restrict__ s, bf16* __restrict__ d, int n4) {
    int i = blockIdx.x * 256 + threadIdx.x;
    if (i < n4) {
        float4 v = ((const float4*)s)[i];
        ((uint2*)d)[i] = make_uint2(packbf(v.x, v.y), packbf(v.z, v.w));
    }
}

// ---------------- bias+mask table: [wtype][head][row][col] bf16 ----------------
__global__ void btab_kernel(const float* __restrict__ relt, bf16* __restrict__ btab) {
    int gid = blockIdx.x * 256 + threadIdx.x;       // one bf16x2 per thread
    if (gid >= 8 * NHEAD * NPAD * (NPAD / 2)) return;
    int c2   = gid % (NPAD / 2);
    int rest = gid / (NPAD / 2);
    int row  = rest % NPAD; rest /= NPAD;
    int head = rest & 3;
    int wt   = rest >> 2;
    bool rowpad = row >= NTOK;
    int tn = 0, hn = 0, wn_ = 0, regn = 0;
    if (!rowpad) {
        tn = row / 49; hn = (row / 7) % 7; wn_ = row % 7;
        int rd = (wt & 4) ? (tn  < 4 ? 1 : 2) : 0;
        int rh = (wt & 2) ? (hn  < 4 ? 1 : 2) : 0;
        int rw = (wt & 1) ? (wn_ < 4 ? 1 : 2) : 0;
        regn = rd * 9 + rh * 3 + rw;
    }
    float v[2];
    #pragma unroll
    for (int e = 0; e < 2; ++e) {
        int col = c2 * 2 + e;
        if (col >= NTOK)      v[e] = -100.f;
        else if (rowpad)      v[e] = 0.f;
        else {
            int tm = col / 49, hm = (col / 7) % 7, wm = col % 7;
            int rd = (wt & 4) ? (tm < 4 ? 1 : 2) : 0;
            int rh = (wt & 2) ? (hm < 4 ? 1 : 2) : 0;
            int rw = (wt & 1) ? (wm < 4 ? 1 : 2) : 0;
            int regm = rd * 9 + rh * 3 + rw;
            int idx = (tn - tm + 7) * 169 + (hn - hm + 6) * 13 + (wn_ - wm + 6);
            float b = relt[idx * NHEAD + head];
            v[e] = (regn == regm) ? b : b - 100.f;
        }
    }
    ((uint32_t*)btab)[gid] = packbf(v[0], v[1]);
}

// ---------------- LN (+optional shift/window-partition), bf16 out ----------------
template<bool SHIFT>
__global__ void __launch_bounds__(256) ln_kernel(const float* __restrict__ x,
                                                 const float* __restrict__ gw,
                                                 const float* __restrict__ gb,
                                                 bf16* __restrict__ out) {
    int row  = blockIdx.x * 8 + (threadIdx.x >> 5);
    int lane = threadIdx.x & 31;
    int src;
    if (SHIFT) {
        int w = row / NTOK, n = row % NTOK;
        int dblk = w >> 6, hblk = (w >> 3) & 7, wblk = w & 7;
        int t = n / 49, hh = (n / 7) % 7, ww = n % 7;
        int gd = (dblk * 8 + t + 4) & 15;
        int gh = hblk * 7 + hh + 3; if (gh >= 56) gh -= 56;
        int gx = wblk * 7 + ww + 3; if (gx >= 56) gx -= 56;
        src = (gd * 56 + gh) * 56 + gx;
    } else {
        src = row;
    }
    float4 v = *(const float4*)(x + (size_t)src * CC + lane * 4);
    float s  = v.x + v.y + v.z + v.w;
    float ss = v.x*v.x + v.y*v.y + v.z*v.z + v.w*v.w;
    #pragma unroll
    for (int o = 16; o; o >>= 1) {
        s  += __shfl_xor_sync(~0u, s,  o);
        ss += __shfl_xor_sync(~0u, ss, o);
    }
    float mu  = s * (1.f / CC);
    float var = ss * (1.f / CC) - mu * mu;
    float rs  = rsqrtf(var + 1e-5f);
    float4 gwv = *(const float4*)(gw + lane * 4);
    float4 gbv = *(const float4*)(gb + lane * 4);
    *(uint2*)(out + (size_t)row * CC + lane * 4) = make_uint2(
        packbf((v.x - mu) * rs * gwv.x + gbv.x, (v.y - mu) * rs * gwv.y + gbv.y),
        packbf((v.z - mu) * rs * gwv.z + gbv.z, (v.w - mu) * rs * gwv.w + gbv.w));
}

// ---------------- bf16 tensor-core GEMM (mma.sync m16n8k16) ----------------
template<int EPI, int ND, int KK>
__global__ void __launch_bounds__(256) mgemm(const bf16* __restrict__ A,
                                             const bf16* __restrict__ B,
                                             const float* __restrict__ bias,
                                             const float* __restrict__ extra,
                                             void* __restrict__ outv) {
    extern __shared__ char smc[];
    const uint32_t smb = (uint32_t)__cvta_generic_to_shared(smc);
    const int tid = threadIdx.x, lane = tid & 31, warp = tid >> 5;
    const int wm = warp >> 2, wn = warp & 3;
    const int m0 = blockIdx.x * 128, n0 = blockIdx.y * 128;
    constexpr int NK = KK / 64;

    float c[4][4][4];
    #pragma unroll
    for (int a = 0; a < 4; ++a)
        #pragma unroll
        for (int b = 0; b < 4; ++b)
            #pragma unroll
            for (int e = 0; e < 4; ++e) c[a][b][e] = 0.f;

    auto load = [&](int kt, int st) {
        uint32_t ab = smb + st * 32768;
        uint32_t bb = ab + 16384;
        #pragma unroll
        for (int i = 0; i < 4; ++i) {
            int cid = tid + i * 256;
            int row = cid >> 3, kb = (cid & 7) * 16;
            cp16(ab + swz(row, kb), (const char*)(A + (size_t)(m0 + row) * KK + kt * 64) + kb);
            cp16(bb + swz(row, kb), (const char*)(B + (size_t)(n0 + row) * KK + kt * 64) + kb);
        }
        asm volatile("cp.async.commit_group;\n");
    };

    load(0, 0);
    for (int kt = 0; kt < NK; ++kt) {
        if (kt + 1 < NK) {
            load(kt + 1, (kt + 1) & 1);
            asm volatile("cp.async.wait_group 1;\n");
        } else {
            asm volatile("cp.async.wait_group 0;\n");
        }
        __syncthreads();
        uint32_t ab = smb + (kt & 1) * 32768, bb = ab + 16384;
        #pragma unroll
        for (int ks = 0; ks < 4; ++ks) {
            uint32_t af[4][4], bfr[4][2];
            #pragma unroll
            for (int mi = 0; mi < 4; ++mi) {
                int row = wm * 64 + mi * 16 + (lane & 15);
                int kb  = ks * 32 + ((lane & 16) ? 16 : 0);
                LDSM4(af[mi], ab + swz(row, kb));
            }
            #pragma unroll
            for (int p = 0; p < 2; ++p) {
                int row = wn * 32 + p * 16 + (lane & 7) + ((lane & 16) ? 8 : 0);
                int kb  = ks * 32 + ((lane & 8) ? 16 : 0);
                uint32_t r4[4];
                LDSM4(r4, bb + swz(row, kb));
                bfr[p*2][0] = r4[0]; bfr[p*2][1] = r4[1];
                bfr[p*2+1][0] = r4[2]; bfr[p*2+1][1] = r4[3];
            }
            #pragma unroll
            for (int mi = 0; mi < 4; ++mi)
                #pragma unroll
                for (int ni = 0; ni < 4; ++ni)
                    MMA16816(c[mi][ni], af[mi][0], af[mi][1], af[mi][2], af[mi][3],
                             bfr[ni][0], bfr[ni][1]);
        }
        __syncthreads();
    }

    const int colb = n0 + wn * 32 + (lane & 3) * 2;
    #pragma unroll
    for (int mi = 0; mi < 4; ++mi) {
        #pragma unroll
        for (int h = 0; h < 2; ++h) {
            int m = m0 + wm * 64 + mi * 16 + (lane >> 2) + h * 8;
            if (EPI == 0) {                 // QKV scatter (+scale q) -> bf16
                int w = m / NTOK, n = m % NTOK;
                bf16* out = (bf16*)outv;
                #pragma unroll
                for (int ni = 0; ni < 4; ++ni) {
                    int j = colb + ni * 8;
                    float v0 = c[mi][ni][h*2+0] + bias[j];
                    float v1 = c[mi][ni][h*2+1] + bias[j+1];
                    int sel = j >> 7, hd = (j >> 5) & 3, dch = j & 31;
                    if (sel == 0) { v0 *= SCALE_Q; v1 *= SCALE_Q; }
                    *(uint32_t*)(out + (size_t)(((sel*NWIN + w)*NHEAD + hd)*NTOK + n)*HEADD + dch)
                        = packbf(v0, v1);
                }
            } else if (EPI == 1) {          // proj + window-reverse + shift + residual
                int w = m / NTOK, n = m % NTOK;
                int dblk = w >> 6, hblk = (w >> 3) & 7, wblk = w & 7;
                int t = n / 49, hh = (n / 7) % 7, ww = n % 7;
                int gd = (dblk * 8 + t + 4) & 15;
                int gh = hblk * 7 + hh + 3; if (gh >= 56) gh -= 56;
                int gx = wblk * 7 + ww + 3; if (gx >= 56) gx -= 56;
                size_t lin = ((size_t)(gd * 56 + gh) * 56 + gx) * CC;
                float* out = (float*)outv;
                #pragma unroll
                for (int ni = 0; ni < 4; ++ni) {
                    int j = colb + ni * 8;
                    float2 e = *(const float2*)(extra + lin + j);
                    *(float2*)(out + lin + j) = make_float2(
                        c[mi][ni][h*2+0] + bias[j]   + e.x,
                        c[mi][ni][h*2+1] + bias[j+1] + e.y);
                }
            } else if (EPI == 2) {          // FC1 + exact GELU -> bf16
                bf16* out = (bf16*)outv;
                #pragma unroll
                for (int ni = 0; ni < 4; ++ni) {
                    int j = colb + ni * 8;
                    float v0 = c[mi][ni][h*2+0] + bias[j];
                    float v1 = c[mi][ni][h*2+1] + bias[j+1];
                    v0 = 0.5f * v0 * (1.f + erff(v0 * 0.70710678118654752f));
                    v1 = 0.5f * v1 * (1.f + erff(v1 * 0.70710678118654752f));
                    *(uint32_t*)(out + (size_t)m * HIDD + j) = packbf(v0, v1);
                }
            } else {                        // FC2 + residual -> final fp32 out
                float* out = (float*)outv;
                #pragma unroll
                for (int ni = 0; ni < 4; ++ni) {
                    int j = colb + ni * 8;
                    float2 e = *(const float2*)(extra + (size_t)m * CC + j);
                    *(float2*)(out + (size_t)m * CC + j) = make_float2(
                        c[mi][ni][h*2+0] + bias[j]   + e.x,
                        c[mi][ni][h*2+1] + bias[j+1] + e.y);
                }
            }
        }
    }
}

// ---------------- bf16 tensor-core attention: one block per (window, head) ----------------
__global__ void __launch_bounds__(256) attn_mma(const bf16* __restrict__ qkv,
                                                const bf16* __restrict__ btab,
                                                bf16* __restrict__ y) {
    const int w = blockIdx.x >> 2, head = blockIdx.x & 3;
    extern __shared__ char sm[];
    const uint32_t smb = (uint32_t)__cvta_generic_to_shared(sm);
    const uint32_t ksb = smb, vsb = smb + 32000;   // 400 rows x 80B each

    const int tid = threadIdx.x, lane = tid & 31, warp = tid >> 5;
    const size_t hw = ((size_t)(w * NHEAD + head)) * NTOK * HEADD;
    const bf16* qb = qkv + hw;
    const bf16* kb = qkv + (size_t)MROWS * CC + hw;
    const bf16* vb = qkv + 2 * (size_t)MROWS * CC + hw;

    // zero pad rows 392..399 (640 B per buffer)
    for (int i = tid; i < 320; i += 256) {
        int buf = (i >= 160);
        int j = i - buf * 160;
        *(uint32_t*)(sm + buf * 32000 + 392 * 80 + j * 4) = 0u;
    }
    // stage K,V (coalesced cp.async, 16B chunks into 80B-stride rows)
    for (int i = tid; i < NTOK * 4; i += 256) {
        int row = i >> 2, off = i & 3;
        cp16(ksb + row * 80 + off * 16, kb + row * 32 + off * 8);
        cp16(vsb + row * 80 + off * 16, vb + row * 32 + off * 8);
    }
    asm volatile("cp.async.commit_group;\n");
    asm volatile("cp.async.wait_group 0;\n");
    __syncthreads();

    const int wtype = ((w >> 6) << 2) | ((((w >> 3) & 7) == 7) ? 2 : 0) | (((w & 7) == 7) ? 1 : 0);
    const bf16* btb = btab + ((size_t)(wtype * NHEAD + head)) * NPAD * NPAD;

    const int r  = lane >> 2, c2 = (lane & 3) * 2;
    const int lrow = (lane & 7) + ((lane & 16) ? 8 : 0);
    const int loff = (lane & 8) ? 16 : 0;

    for (int mt = warp; mt < 25; mt += 8) {
        const int m0r = mt * 16;
        // Q a-fragments straight from gmem (already SCALE_Q'd)
        uint32_t qa[2][4];
        #pragma unroll
        for (int kt = 0; kt < 2; ++kt) {
            qa[kt][0] = *(const uint32_t*)(qb + (m0r + r    ) * 32 + kt * 16 +     c2);
            qa[kt][1] = *(const uint32_t*)(qb + (m0r + r + 8) * 32 + kt * 16 +     c2);
            qa[kt][2] = *(const uint32_t*)(qb + (m0r + r    ) * 32 + kt * 16 + 8 + c2);
            qa[kt][3] = *(const uint32_t*)(qb + (m0r + r + 8) * 32 + kt * 16 + 8 + c2);
        }
        float oc[4][4];
        #pragma unroll
        for (int a = 0; a < 4; ++a)
            #pragma unroll
            for (int e = 0; e < 4; ++e) oc[a][e] = 0.f;
        float rs0 = 0.f, rs1 = 0.f;

        for (int np = 0; np < 25; ++np) {
            uint32_t kadr = ksb + (np * 16 + lrow) * 80 + loff;
            uint32_t kf0[4], kf1[4];
            LDSM4(kf0, kadr);
            LDSM4(kf1, kadr + 32);
            float sA[4] = {0.f, 0.f, 0.f, 0.f};
            float sB[4] = {0.f, 0.f, 0.f, 0.f};
            MMA16816(sA, qa[0][0], qa[0][1], qa[0][2], qa[0][3], kf0[0], kf0[1]);
            MMA16816(sA, qa[1][0], qa[1][1], qa[1][2], qa[1][3], kf1[0], kf1[1]);
            MMA16816(sB, qa[0][0], qa[0][1], qa[0][2], qa[0][3], kf0[2], kf0[3]);
            MMA16816(sB, qa[1][0], qa[1][1], qa[1][2], qa[1][3], kf1[2], kf1[3]);
            // bias + mask (bf16x2 loads)
            const bf16* bp = btb + (size_t)(m0r + r) * NPAD + np * 16 + c2;
            float2 fA0 = unpackbf(*(const uint32_t*)(bp));
            float2 fA1 = unpackbf(*(const uint32_t*)(bp + 8 * NPAD));
            float2 fB0 = unpackbf(*(const uint32_t*)(bp + 8));
            float2 fB1 = unpackbf(*(const uint32_t*)(bp + 8 * NPAD + 8));
            float e0 = __expf(sA[0] + fA0.x), e1 = __expf(sA[1] + fA0.y);
            float e2 = __expf(sA[2] + fA1.x), e3 = __expf(sA[3] + fA1.y);
            float e4 = __expf(sB[0] + fB0.x), e5 = __expf(sB[1] + fB0.y);
            float e6 = __expf(sB[2] + fB1.x), e7 = __expf(sB[3] + fB1.y);
            rs0 += e0 + e1 + e4 + e5;
            rs1 += e2 + e3 + e6 + e7;
            uint32_t pa0 = packbf(e0, e1), pa1 = packbf(e2, e3);
            uint32_t pa2 = packbf(e4, e5), pa3 = packbf(e6, e7);
            // V b-fragments (transposed by ldmatrix)
            uint32_t vadr = vsb + (np * 16 + lrow) * 80 + loff;
            uint32_t vf0[4], vf1[4];
            LDSM4T(vf0, vadr);
            LDSM4T(vf1, vadr + 32);
            MMA16816(oc[0], pa0, pa1, pa2, pa3, vf0[0], vf0[2]);
            MMA16816(oc[1], pa0, pa1, pa2, pa3, vf0[1], vf0[3]);
            MMA16816(oc[2], pa0, pa1, pa2, pa3, vf1[0], vf1[2]);
            MMA16816(oc[3], pa0, pa1, pa2, pa3, vf1[1], vf1[3]);
        }
        // row-sum reduce across the quad owning each row
        rs0 += __shfl_xor_sync(~0u, rs0, 1); rs0 += __shfl_xor_sync(~0u, rs0, 2);
        rs1 += __shfl_xor_sync(~0u, rs1, 1); rs1 += __shfl_xor_sync(~0u, rs1, 2);
        float i0 = 1.f / rs0, i1 = 1.f / rs1;
        // store normalized output (bf16) — row m0r+r always < 392
        {
            size_t yb = ((size_t)(w * NTOK + m0r + r)) * CC + head * HEADD + c2;
            #pragma unroll
            for (int dt = 0; dt < 4; ++dt)
                *(uint32_t*)(y + yb + dt * 8) = packbf(oc[dt][0] * i0, oc[dt][1] * i0);
        }
        if (m0r + r + 8 < NTOK) {
            size_t yb = ((size_t)(w * NTOK + m0r + r + 8)) * CC + head * HEADD + c2;
            #pragma unroll
            for (int dt = 0; dt < 4; ++dt)
                *(uint32_t*)(y + yb + dt * 8) = packbf(oc[dt][2] * i1, oc[dt][3] * i1);
        }
    }
}

// ---------------- launch ----------------
extern "C" void kernel_launch(void* const* d_in, const int* in_sizes, int n_in,
                              void* d_out, int out_size) {
    (void)in_sizes; (void)n_in; (void)out_size;
    const float* x     = (const float*)d_in[0];
    const float* n1w   = (const float*)d_in[1];
    const float* n1b   = (const float*)d_in[2];
    const float* qkvw  = (const float*)d_in[3];
    const float* qkvb  = (const float*)d_in[4];
    const float* relt  = (const float*)d_in[5];
    const float* projw = (const float*)d_in[6];
    const float* projb = (const float*)d_in[7];
    const float* n2w   = (const float*)d_in[8];
    const float* n2b   = (const float*)d_in[9];
    const float* fc1w  = (const float*)d_in[10];
    const float* fc1b  = (const float*)d_in[11];
    const float* fc2w  = (const float*)d_in[12];
    const float* fc2b  = (const float*)d_in[13];

    bf16 *win, *qkvB, *yB, *m1, *hid, *wb, *btab;
    float *x1;
    cudaGetSymbolAddress((void**)&win,  g_win);
    cudaGetSymbolAddress((void**)&qkvB, g_qkv);
    cudaGetSymbolAddress((void**)&yB,   g_y);
    cudaGetSymbolAddress((void**)&x1,   g_x1);
    cudaGetSymbolAddress((void**)&m1,   g_m1);
    cudaGetSymbolAddress((void**)&hid,  g_hid);
    cudaGetSymbolAddress((void**)&wb,   g_wb);
    cudaGetSymbolAddress((void**)&btab, g_btab);

    cudaFuncSetAttribute(attn_mma, cudaFuncAttributeMaxDynamicSharedMemorySize, SMEM_ATT);
    cudaFuncSetAttribute(mgemm<0,384,128>, cudaFuncAttributeMaxDynamicSharedMemorySize, SMEM_GEMM);
    cudaFuncSetAttribute(mgemm<1,128,128>, cudaFuncAttributeMaxDynamicSharedMemorySize, SMEM_GEMM);
    cudaFuncSetAttribute(mgemm<2,512,128>, cudaFuncAttributeMaxDynamicSharedMemorySize, SMEM_GEMM);
    cudaFuncSetAttribute(mgemm<3,128,512>, cudaFuncAttributeMaxDynamicSharedMemorySize, SMEM_GEMM);

    cvt_kernel<<<48, 256>>>(qkvw,  wb,          12288);
    cvt_kernel<<<16, 256>>>(projw, wb + 49152,  4096);
    cvt_kernel<<<64, 256>>>(fc1w,  wb + 65536,  16384);
    cvt_kernel<<<64, 256>>>(fc2w,  wb + 131072, 16384);
    btab_kernel<<<10000, 256>>>(relt, btab);

    ln_kernel<true><<<MROWS / 8, 256>>>(x, n1w, n1b, win);
    mgemm<0, 384, 128><<<dim3(392, 3), 256, SMEM_GEMM>>>(win, wb, qkvb, nullptr, qkvB);
    attn_mma<<<NWIN * NHEAD, 256, SMEM_ATT>>>(qkvB, btab, yB);
    mgemm<1, 128, 128><<<dim3(392, 1), 256, SMEM_GEMM>>>(yB, wb + 49152, projb, x, x1);
    ln_kernel<false><<<MROWS / 8, 256>>>(x1, n2w, n2b, m1);
    mgemm<2, 512, 128><<<dim3(392, 4), 256, SMEM_GEMM>>>(m1, wb + 65536, fc1b, nullptr, hid);
    mgemm<3, 128, 512><<<dim3(392, 1), 256, SMEM_GEMM>>>(hid, wb + 131072, fc2b, x1, (float*)d_out);
}

// round 5
// speedup vs baseline: 4.2888x; 1.0068x over previous
#include <cuda_runtime.h>
#include <cuda_bf16.h>
#include <math.h>
#include <stdint.h>

// ---------------- problem constants ----------------
#define CC      128
#define NHEAD   4
#define HEADD   32
#define NTOK    392
#define NPAD    400
#define NWIN    128
#define MROWS   50176
#define HIDD    512
#define SCALE_Q 0.17677669529663687f
#define SMEM_ATT  64000     // attention: Ks + Vs, 400 rows x 80B
#define SMEM_G2   65536     // gemm: 2 stages x (A 16KB + B 16KB)

typedef __nv_bfloat16 bf16;

// ---------------- scratch (device globals) ----------------
__device__ __align__(16) bf16  g_win[MROWS * CC];
__device__ __align__(16) bf16  g_qkv[3 * MROWS * CC];   // bf16 (sel,w,head,n,d)
__device__ __align__(16) bf16  g_y[MROWS * CC];
__device__ __align__(16) float g_x1[MROWS * CC];
__device__ __align__(16) bf16  g_m1[MROWS * CC];
__device__ __align__(16) bf16  g_hid[MROWS * HIDD];
__device__ __align__(16) bf16  g_wb[196608];
__device__ __align__(16) bf16  g_btab[8 * NHEAD * NPAD * NPAD];

// ---------------- asm helpers ----------------
__device__ __forceinline__ void cp16(uint32_t dst, const void* src) {
    asm volatile("cp.async.cg.shared.global [%0], [%1], 16;\n" :: "r"(dst), "l"(src));
}
__device__ __forceinline__ uint32_t swz(int row, int kb) {
    return (uint32_t)((row << 7) + (kb ^ ((row & 7) << 4)));
}
#define LDSM4(R, addr) \
    asm volatile("ldmatrix.sync.aligned.m8n8.x4.shared.b16 {%0,%1,%2,%3}, [%4];\n" \
        : "=r"((R)[0]), "=r"((R)[1]), "=r"((R)[2]), "=r"((R)[3]) : "r"(addr))
#define LDSM4T(R, addr) \
    asm volatile("ldmatrix.sync.aligned.m8n8.x4.trans.shared.b16 {%0,%1,%2,%3}, [%4];\n" \
        : "=r"((R)[0]), "=r"((R)[1]), "=r"((R)[2]), "=r"((R)[3]) : "r"(addr))
#define MMA16816(d, a0,a1,a2,a3, b0,b1) \
    asm volatile("mma.sync.aligned.m16n8k16.row.col.f32.bf16.bf16.f32 " \
        "{%0,%1,%2,%3}, {%4,%5,%6,%7}, {%8,%9}, {%0,%1,%2,%3};\n" \
        : "+f"((d)[0]), "+f"((d)[1]), "+f"((d)[2]), "+f"((d)[3]) \
        : "r"(a0), "r"(a1), "r"(a2), "r"(a3), "r"(b0), "r"(b1))

__device__ __forceinline__ uint32_t packbf(float a, float b) {
    __nv_bfloat162 p = __floats2bfloat162_rn(a, b);
    return *(uint32_t*)&p;
}
__device__ __forceinline__ float2 unpackbf(uint32_t u) {
    return __bfloat1622float2(*(__nv_bfloat162*)&u);
}

// ---------------- all weights fp32 -> bf16 in ONE launch ----------------
// dst layout (bf16 elems): qkv @0, proj @49152, fc1 @65536, fc2 @131072
__global__ void cvt_all(const float* __restrict__ s0, const float* __restrict__ s1,
                        const float* __restrict__ s2, const float* __restrict__ s3,
                        bf16* __restrict__ d) {
    int i = blockIdx.x * 256 + threadIdx.x;        // float4 index, 49152 total
    if (i >= 49152) return;
    const float* s; int off;
    if (i < 12288)      { s = s0; off = 0; }
    else if (i < 16384) { s = s1; off = 12288; }
    else if (i < 32768) { s = s2; off = 16384; }
    else                { s = s3; off = 32768; }
    float4 v = ((const float4*)s)[i - off];
    ((uint2*)d)[i] = make_uint2(packbf(v.x, v.y), packbf(v.z, v.w));
}

// ---------------- bias+mask table ----------------
__global__ void btab_kernel(const float* __restrict__ relt, bf16* __restrict__ btab) {
    int gid = blockIdx.x * 256 + threadIdx.x;
    if (gid >= 8 * NHEAD * NPAD * (NPAD / 2)) return;
    int c2   = gid % (NPAD / 2);
    int rest = gid / (NPAD / 2);
    int row  = rest % NPAD; rest /= NPAD;
    int head = rest & 3;
    int wt   = rest >> 2;
    bool rowpad = row >= NTOK;
    int tn = 0, hn = 0, wn_ = 0, regn = 0;
    if (!rowpad) {
        tn = row / 49; hn = (row / 7) % 7; wn_ = row % 7;
        int rd = (wt & 4) ? (tn  < 4 ? 1 : 2) : 0;
        int rh = (wt & 2) ? (hn  < 4 ? 1 : 2) : 0;
        int rw = (wt & 1) ? (wn_ < 4 ? 1 : 2) : 0;
        regn = rd * 9 + rh * 3 + rw;
    }
    float v[2];
    #pragma unroll
    for (int e = 0; e < 2; ++e) {
        int col = c2 * 2 + e;
        if (col >= NTOK)      v[e] = -100.f;
        else if (rowpad)      v[e] = 0.f;
        else {
            int tm = col / 49, hm = (col / 7) % 7, wm = col % 7;
            int rd = (wt & 4) ? (tm < 4 ? 1 : 2) : 0;
            int rh = (wt & 2) ? (hm < 4 ? 1 : 2) : 0;
            int rw = (wt & 1) ? (wm < 4 ? 1 : 2) : 0;
            int regm = rd * 9 + rh * 3 + rw;
            int idx = (tn - tm + 7) * 169 + (hn - hm + 6) * 13 + (wn_ - wm + 6);
            float b = relt[idx * NHEAD + head];
            v[e] = (regn == regm) ? b : b - 100.f;
        }
    }
    ((uint32_t*)btab)[gid] = packbf(v[0], v[1]);
}

// ---------------- LN (+optional shift/window-partition), bf16 out ----------------
template<bool SHIFT>
__global__ void __launch_bounds__(256) ln_kernel(const float* __restrict__ x,
                                                 const float* __restrict__ gw,
                                                 const float* __restrict__ gb,
                                                 bf16* __restrict__ out) {
    int row  = blockIdx.x * 8 + (threadIdx.x >> 5);
    int lane = threadIdx.x & 31;
    int src;
    if (SHIFT) {
        int w = row / NTOK, n = row % NTOK;
        int dblk = w >> 6, hblk = (w >> 3) & 7, wblk = w & 7;
        int t = n / 49, hh = (n / 7) % 7, ww = n % 7;
        int gd = (dblk * 8 + t + 4) & 15;
        int gh = hblk * 7 + hh + 3; if (gh >= 56) gh -= 56;
        int gx = wblk * 7 + ww + 3; if (gx >= 56) gx -= 56;
        src = (gd * 56 + gh) * 56 + gx;
    } else {
        src = row;
    }
    float4 v = *(const float4*)(x + (size_t)src * CC + lane * 4);
    float s  = v.x + v.y + v.z + v.w;
    float ss = v.x*v.x + v.y*v.y + v.z*v.z + v.w*v.w;
    #pragma unroll
    for (int o = 16; o; o >>= 1) {
        s  += __shfl_xor_sync(~0u, s,  o);
        ss += __shfl_xor_sync(~0u, ss, o);
    }
    float mu  = s * (1.f / CC);
    float var = ss * (1.f / CC) - mu * mu;
    float rs  = rsqrtf(var + 1e-5f);
    float4 gwv = *(const float4*)(gw + lane * 4);
    float4 gbv = *(const float4*)(gb + lane * 4);
    *(uint2*)(out + (size_t)row * CC + lane * 4) = make_uint2(
        packbf((v.x - mu) * rs * gwv.x + gbv.x, (v.y - mu) * rs * gwv.y + gbv.y),
        packbf((v.z - mu) * rs * gwv.z + gbv.z, (v.w - mu) * rs * gwv.w + gbv.w));
}

// ---------------- bf16 HMMA GEMM v2: 128x128 CTA, 4 warps @ 64x64 ----------------
// out(M,ND) = A(M,KK) @ B(ND,KK)^T + bias, fused epilogue EPI.
template<int EPI, int ND, int KK>
__global__ void __launch_bounds__(128) mgemm2(const bf16* __restrict__ A,
                                              const bf16* __restrict__ B,
                                              const float* __restrict__ bias,
                                              const float* __restrict__ extra,
                                              void* __restrict__ outv) {
    extern __shared__ char smc[];
    const uint32_t smb = (uint32_t)__cvta_generic_to_shared(smc);
    const int tid = threadIdx.x, lane = tid & 31, warp = tid >> 5;
    const int wm = warp >> 1, wn = warp & 1;          // 2x2 warp grid, 64x64 tiles
    const int m0 = blockIdx.x * 128, n0 = blockIdx.y * 128;
    constexpr int NCHUNK = KK / 64;

    float c[4][8][4];
    #pragma unroll
    for (int a = 0; a < 4; ++a)
        #pragma unroll
        for (int b = 0; b < 8; ++b)
            #pragma unroll
            for (int e = 0; e < 4; ++e) c[a][b][e] = 0.f;

    auto load = [&](int ch, int st) {
        uint32_t ab = smb + st * 32768, bb = ab + 16384;
        const char* Ap = (const char*)(A + (size_t)m0 * KK + ch * 64);
        const char* Bp = (const char*)(B + (size_t)n0 * KK + ch * 64);
        #pragma unroll
        for (int i = 0; i < 8; ++i) {
            int cid = tid + i * 128;                   // 1024 chunks each
            int row = cid >> 3, kb = (cid & 7) * 16;
            cp16(ab + swz(row, kb), Ap + (size_t)row * (KK * 2) + kb);
            cp16(bb + swz(row, kb), Bp + (size_t)row * (KK * 2) + kb);
        }
        asm volatile("cp.async.commit_group;\n");
    };

    load(0, 0);
    if (NCHUNK > 1) load(1, 1);
    asm volatile("cp.async.wait_group %0;\n" :: "n"(1));
    if (NCHUNK == 1) asm volatile("cp.async.wait_group 0;\n");
    __syncthreads();

    #pragma unroll 1
    for (int ch = 0; ch < NCHUNK; ++ch) {
        const int st = ch & 1;
        const uint32_t ab = smb + st * 32768, bb = ab + 16384;
        uint32_t af[2][4][4], bfr[2][4][4];
        auto ldf = [&](int ks, int u) {
            #pragma unroll
            for (int mi = 0; mi < 4; ++mi) {
                int row = wm * 64 + mi * 16 + (lane & 15);
                int kb  = ks * 32 + ((lane & 16) ? 16 : 0);
                LDSM4(af[u][mi], ab + swz(row, kb));
            }
            #pragma unroll
            for (int p = 0; p < 4; ++p) {
                int row = wn * 64 + p * 16 + (lane & 7) + ((lane & 16) ? 8 : 0);
                int kb  = ks * 32 + ((lane & 8) ? 16 : 0);
                LDSM4(bfr[u][p], bb + swz(row, kb));
            }
        };
        ldf(0, 0);
        #pragma unroll
        for (int ks = 0; ks < 4; ++ks) {
            if (ks < 3) ldf(ks + 1, (ks + 1) & 1);
            const int u = ks & 1;
            #pragma unroll
            for (int mi = 0; mi < 4; ++mi)
                #pragma unroll
                for (int p = 0; p < 4; ++p) {
                    MMA16816(c[mi][p*2],   af[u][mi][0], af[u][mi][1], af[u][mi][2], af[u][mi][3],
                             bfr[u][p][0], bfr[u][p][1]);
                    MMA16816(c[mi][p*2+1], af[u][mi][0], af[u][mi][1], af[u][mi][2], af[u][mi][3],
                             bfr[u][p][2], bfr[u][p][3]);
                }
        }
        __syncthreads();
        if (ch + 2 < NCHUNK) load(ch + 2, st);
        if (ch + 1 < NCHUNK) {
            if (ch + 2 < NCHUNK) asm volatile("cp.async.wait_group %0;\n" :: "n"(1));
            else                 asm volatile("cp.async.wait_group 0;\n");
            __syncthreads();
        }
    }

    // ---------------- epilogue ----------------
    const int colb = n0 + wn * 64 + (lane & 3) * 2;
    #pragma unroll
    for (int mi = 0; mi < 4; ++mi) {
        #pragma unroll
        for (int h = 0; h < 2; ++h) {
            int m = m0 + wm * 64 + mi * 16 + (lane >> 2) + h * 8;
            if (EPI == 0) {                 // QKV scatter (+scale q) -> bf16
                int w = m / NTOK, n = m % NTOK;
                bf16* out = (bf16*)outv;
                #pragma unroll
                for (int ni = 0; ni < 8; ++ni) {
                    int j = colb + ni * 8;
                    float v0 = c[mi][ni][h*2+0] + bias[j];
                    float v1 = c[mi][ni][h*2+1] + bias[j+1];
                    int sel = j >> 7, hd = (j >> 5) & 3, dch = j & 31;
                    if (sel == 0) { v0 *= SCALE_Q; v1 *= SCALE_Q; }
                    *(uint32_t*)(out + (size_t)(((sel*NWIN + w)*NHEAD + hd)*NTOK + n)*HEADD + dch)
                        = packbf(v0, v1);
                }
            } else if (EPI == 1) {          // proj + window-reverse + shift + residual
                int w = m / NTOK, n = m % NTOK;
                int dblk = w >> 6, hblk = (w >> 3) & 7, wblk = w & 7;
                int t = n / 49, hh = (n / 7) % 7, ww = n % 7;
                int gd = (dblk * 8 + t + 4) & 15;
                int gh = hblk * 7 + hh + 3; if (gh >= 56) gh -= 56;
                int gx = wblk * 7 + ww + 3; if (gx >= 56) gx -= 56;
                size_t lin = ((size_t)(gd * 56 + gh) * 56 + gx) * CC;
                float* out = (float*)outv;
                #pragma unroll
                for (int ni = 0; ni < 8; ++ni) {
                    int j = colb + ni * 8;
                    float2 e = *(const float2*)(extra + lin + j);
                    *(float2*)(out + lin + j) = make_float2(
                        c[mi][ni][h*2+0] + bias[j]   + e.x,
                        c[mi][ni][h*2+1] + bias[j+1] + e.y);
                }
            } else if (EPI == 2) {          // FC1 + exact GELU -> bf16
                bf16* out = (bf16*)outv;
                #pragma unroll
                for (int ni = 0; ni < 8; ++ni) {
                    int j = colb + ni * 8;
                    float v0 = c[mi][ni][h*2+0] + bias[j];
                    float v1 = c[mi][ni][h*2+1] + bias[j+1];
                    v0 = 0.5f * v0 * (1.f + erff(v0 * 0.70710678118654752f));
                    v1 = 0.5f * v1 * (1.f + erff(v1 * 0.70710678118654752f));
                    *(uint32_t*)(out + (size_t)m * HIDD + j) = packbf(v0, v1);
                }
            } else {                        // FC2 + residual -> final fp32 out
                float* out = (float*)outv;
                #pragma unroll
                for (int ni = 0; ni < 8; ++ni) {
                    int j = colb + ni * 8;
                    float2 e = *(const float2*)(extra + (size_t)m * CC + j);
                    *(float2*)(out + (size_t)m * CC + j) = make_float2(
                        c[mi][ni][h*2+0] + bias[j]   + e.x,
                        c[mi][ni][h*2+1] + bias[j+1] + e.y);
                }
            }
        }
    }
}

// ---------------- bf16 tensor-core attention (unchanged from R3) ----------------
__global__ void __launch_bounds__(256) attn_mma(const bf16* __restrict__ qkv,
                                                const bf16* __restrict__ btab,
                                                bf16* __restrict__ y) {
    const int w = blockIdx.x >> 2, head = blockIdx.x & 3;
    extern __shared__ char sm[];
    const uint32_t smb = (uint32_t)__cvta_generic_to_shared(sm);
    const uint32_t ksb = smb, vsb = smb + 32000;

    const int tid = threadIdx.x, lane = tid & 31, warp = tid >> 5;
    const size_t hw = ((size_t)(w * NHEAD + head)) * NTOK * HEADD;
    const bf16* qb = qkv + hw;
    const bf16* kb = qkv + (size_t)MROWS * CC + hw;
    const bf16* vb = qkv + 2 * (size_t)MROWS * CC + hw;

    for (int i = tid; i < 320; i += 256) {
        int buf = (i >= 160);
        int j = i - buf * 160;
        *(uint32_t*)(sm + buf * 32000 + 392 * 80 + j * 4) = 0u;
    }
    for (int i = tid; i < NTOK * 4; i += 256) {
        int row = i >> 2, off = i & 3;
        cp16(ksb + row * 80 + off * 16, kb + row * 32 + off * 8);
        cp16(vsb + row * 80 + off * 16, vb + row * 32 + off * 8);
    }
    asm volatile("cp.async.commit_group;\n");
    asm volatile("cp.async.wait_group 0;\n");
    __syncthreads();

    const int wtype = ((w >> 6) << 2) | ((((w >> 3) & 7) == 7) ? 2 : 0) | (((w & 7) == 7) ? 1 : 0);
    const bf16* btb = btab + ((size_t)(wtype * NHEAD + head)) * NPAD * NPAD;

    const int r  = lane >> 2, c2 = (lane & 3) * 2;
    const int lrow = (lane & 7) + ((lane & 16) ? 8 : 0);
    const int loff = (lane & 8) ? 16 : 0;

    for (int mt = warp; mt < 25; mt += 8) {
        const int m0r = mt * 16;
        uint32_t qa[2][4];
        #pragma unroll
        for (int kt = 0; kt < 2; ++kt) {
            qa[kt][0] = *(const uint32_t*)(qb + (m0r + r    ) * 32 + kt * 16 +     c2);
            qa[kt][1] = *(const uint32_t*)(qb + (m0r + r + 8) * 32 + kt * 16 +     c2);
            qa[kt][2] = *(const uint32_t*)(qb + (m0r + r    ) * 32 + kt * 16 + 8 + c2);
            qa[kt][3] = *(const uint32_t*)(qb + (m0r + r + 8) * 32 + kt * 16 + 8 + c2);
        }
        float oc[4][4];
        #pragma unroll
        for (int a = 0; a < 4; ++a)
            #pragma unroll
            for (int e = 0; e < 4; ++e) oc[a][e] = 0.f;
        float rs0 = 0.f, rs1 = 0.f;

        for (int np = 0; np < 25; ++np) {
            uint32_t kadr = ksb + (np * 16 + lrow) * 80 + loff;
            uint32_t kf0[4], kf1[4];
            LDSM4(kf0, kadr);
            LDSM4(kf1, kadr + 32);
            float sA[4] = {0.f, 0.f, 0.f, 0.f};
            float sB[4] = {0.f, 0.f, 0.f, 0.f};
            MMA16816(sA, qa[0][0], qa[0][1], qa[0][2], qa[0][3], kf0[0], kf0[1]);
            MMA16816(sA, qa[1][0], qa[1][1], qa[1][2], qa[1][3], kf1[0], kf1[1]);
            MMA16816(sB, qa[0][0], qa[0][1], qa[0][2], qa[0][3], kf0[2], kf0[3]);
            MMA16816(sB, qa[1][0], qa[1][1], qa[1][2], qa[1][3], kf1[2], kf1[3]);
            const bf16* bp = btb + (size_t)(m0r + r) * NPAD + np * 16 + c2;
            float2 fA0 = unpackbf(*(const uint32_t*)(bp));
            float2 fA1 = unpackbf(*(const uint32_t*)(bp + 8 * NPAD));
            float2 fB0 = unpackbf(*(const uint32_t*)(bp + 8));
            float2 fB1 = unpackbf(*(const uint32_t*)(bp + 8 * NPAD + 8));
            float e0 = __expf(sA[0] + fA0.x), e1 = __expf(sA[1] + fA0.y);
            float e2 = __expf(sA[2] + fA1.x), e3 = __expf(sA[3] + fA1.y);
            float e4 = __expf(sB[0] + fB0.x), e5 = __expf(sB[1] + fB0.y);
            float e6 = __expf(sB[2] + fB1.x), e7 = __expf(sB[3] + fB1.y);
            rs0 += e0 + e1 + e4 + e5;
            rs1 += e2 + e3 + e6 + e7;
            uint32_t pa0 = packbf(e0, e1), pa1 = packbf(e2, e3);
            uint32_t pa2 = packbf(e4, e5), pa3 = packbf(e6, e7);
            uint32_t vadr = vsb + (np * 16 + lrow) * 80 + loff;
            uint32_t vf0[4], vf1[4];
            LDSM4T(vf0, vadr);
            LDSM4T(vf1, vadr + 32);
            MMA16816(oc[0], pa0, pa1, pa2, pa3, vf0[0], vf0[2]);
            MMA16816(oc[1], pa0, pa1, pa2, pa3, vf0[1], vf0[3]);
            MMA16816(oc[2], pa0, pa1, pa2, pa3, vf1[0], vf1[2]);
            MMA16816(oc[3], pa0, pa1, pa2, pa3, vf1[1], vf1[3]);
        }
        rs0 += __shfl_xor_sync(~0u, rs0, 1); rs0 += __shfl_xor_sync(~0u, rs0, 2);
        rs1 += __shfl_xor_sync(~0u, rs1, 1); rs1 += __shfl_xor_sync(~0u, rs1, 2);
        float i0 = 1.f / rs0, i1 = 1.f / rs1;
        {
            size_t yb = ((size_t)(w * NTOK + m0r + r)) * CC + head * HEADD + c2;
            #pragma unroll
            for (int dt = 0; dt < 4; ++dt)
                *(uint32_t*)(y + yb + dt * 8) = packbf(oc[dt][0] * i0, oc[dt][1] * i0);
        }
        if (m0r + r + 8 < NTOK) {
            size_t yb = ((size_t)(w * NTOK + m0r + r + 8)) * CC + head * HEADD + c2;
            #pragma unroll
            for (int dt = 0; dt < 4; ++dt)
                *(uint32_t*)(y + yb + dt * 8) = packbf(oc[dt][2] * i1, oc[dt][3] * i1);
        }
    }
}

// ---------------- launch ----------------
extern "C" void kernel_launch(void* const* d_in, const int* in_sizes, int n_in,
                              void* d_out, int out_size) {
    (void)in_sizes; (void)n_in; (void)out_size;
    const float* x     = (const float*)d_in[0];
    const float* n1w   = (const float*)d_in[1];
    const float* n1b   = (const float*)d_in[2];
    const float* qkvw  = (const float*)d_in[3];
    const float* qkvb  = (const float*)d_in[4];
    const float* relt  = (const float*)d_in[5];
    const float* projw = (const float*)d_in[6];
    const float* projb = (const float*)d_in[7];
    const float* n2w   = (const float*)d_in[8];
    const float* n2b   = (const float*)d_in[9];
    const float* fc1w  = (const float*)d_in[10];
    const float* fc1b  = (const float*)d_in[11];
    const float* fc2w  = (const float*)d_in[12];
    const float* fc2b  = (const float*)d_in[13];

    bf16 *win, *qkvB, *yB, *m1, *hid, *wb, *btab;
    float *x1;
    cudaGetSymbolAddress((void**)&win,  g_win);
    cudaGetSymbolAddress((void**)&qkvB, g_qkv);
    cudaGetSymbolAddress((void**)&yB,   g_y);
    cudaGetSymbolAddress((void**)&x1,   g_x1);
    cudaGetSymbolAddress((void**)&m1,   g_m1);
    cudaGetSymbolAddress((void**)&hid,  g_hid);
    cudaGetSymbolAddress((void**)&wb,   g_wb);
    cudaGetSymbolAddress((void**)&btab, g_btab);

    cudaFuncSetAttribute(attn_mma, cudaFuncAttributeMaxDynamicSharedMemorySize, SMEM_ATT);
    cudaFuncSetAttribute(mgemm2<0,384,128>, cudaFuncAttributeMaxDynamicSharedMemorySize, SMEM_G2);
    cudaFuncSetAttribute(mgemm2<1,128,128>, cudaFuncAttributeMaxDynamicSharedMemorySize, SMEM_G2);
    cudaFuncSetAttribute(mgemm2<2,512,128>, cudaFuncAttributeMaxDynamicSharedMemorySize, SMEM_G2);
    cudaFuncSetAttribute(mgemm2<3,128,512>, cudaFuncAttributeMaxDynamicSharedMemorySize, SMEM_G2);

    cvt_all<<<192, 256>>>(qkvw, projw, fc1w, fc2w, wb);
    btab_kernel<<<10000, 256>>>(relt, btab);

    ln_kernel<true><<<MROWS / 8, 256>>>(x, n1w, n1b, win);
    mgemm2<0, 384, 128><<<dim3(392, 3), 128, SMEM_G2>>>(win, wb, qkvb, nullptr, qkvB);
    attn_mma<<<NWIN * NHEAD, 256, SMEM_ATT>>>(qkvB, btab, yB);
    mgemm2<1, 128, 128><<<dim3(392, 1), 128, SMEM_G2>>>(yB, wb + 49152, projb, x, x1);
    ln_kernel<false><<<MROWS / 8, 256>>>(x1, n2w, n2b, m1);
    mgemm2<2, 512, 128><<<dim3(392, 4), 128, SMEM_G2>>>(m1, wb + 65536, fc1b, nullptr, hid);
    mgemm2<3, 128, 512><<<dim3(392, 1), 128, SMEM_G2>>>(hid, wb + 131072, fc2b, x1, (float*)d_out);
}

// round 6
// speedup vs baseline: 5.3341x; 1.2437x over previous
#include <cuda_runtime.h>
#include <cuda_bf16.h>
#include <math.h>
#include <stdint.h>

// ---------------- problem constants ----------------
#define CC      128
#define NHEAD   4
#define HEADD   32
#define NTOK    392
#define NPAD    400
#define NWIN    128
#define MROWS   50176
#define HIDD    512
#define SCALE_Q 0.17677669529663687f
#define SMEM_ATT  64000     // attention: Ks + Vs, 400 rows x 80B
#define SMEM_G2   65536     // gemm: 2 stages x (A 16KB + B 16KB)

typedef __nv_bfloat16 bf16;

// ---------------- scratch (device globals) ----------------
__device__ __align__(16) bf16  g_win[MROWS * CC];
__device__ __align__(16) bf16  g_qkv[3 * MROWS * CC];   // bf16 (sel,w,head,n,d)
__device__ __align__(16) bf16  g_y[MROWS * CC];
__device__ __align__(16) float g_x1[MROWS * CC];
__device__ __align__(16) bf16  g_m1[MROWS * CC];
__device__ __align__(16) bf16  g_hid[MROWS * HIDD];
__device__ __align__(16) bf16  g_wb[196608];
__device__ __align__(16) uint4 g_btabf[32 * 625 * 32];  // fragment-major bias+mask

// ---------------- asm helpers ----------------
__device__ __forceinline__ void cp16(uint32_t dst, const void* src) {
    asm volatile("cp.async.cg.shared.global [%0], [%1], 16;\n" :: "r"(dst), "l"(src));
}
__device__ __forceinline__ uint32_t swz(int row, int kb) {
    return (uint32_t)((row << 7) + (kb ^ ((row & 7) << 4)));
}
#define LDSM4(R, addr) \
    asm volatile("ldmatrix.sync.aligned.m8n8.x4.shared.b16 {%0,%1,%2,%3}, [%4];\n" \
        : "=r"((R)[0]), "=r"((R)[1]), "=r"((R)[2]), "=r"((R)[3]) : "r"(addr))
#define LDSM4T(R, addr) \
    asm volatile("ldmatrix.sync.aligned.m8n8.x4.trans.shared.b16 {%0,%1,%2,%3}, [%4];\n" \
        : "=r"((R)[0]), "=r"((R)[1]), "=r"((R)[2]), "=r"((R)[3]) : "r"(addr))
#define MMA16816(d, a0,a1,a2,a3, b0,b1) \
    asm volatile("mma.sync.aligned.m16n8k16.row.col.f32.bf16.bf16.f32 " \
        "{%0,%1,%2,%3}, {%4,%5,%6,%7}, {%8,%9}, {%0,%1,%2,%3};\n" \
        : "+f"((d)[0]), "+f"((d)[1]), "+f"((d)[2]), "+f"((d)[3]) \
        : "r"(a0), "r"(a1), "r"(a2), "r"(a3), "r"(b0), "r"(b1))

__device__ __forceinline__ uint32_t packbf(float a, float b) {
    __nv_bfloat162 p = __floats2bfloat162_rn(a, b);
    return *(uint32_t*)&p;
}
__device__ __forceinline__ float2 unpackbf(uint32_t u) {
    return __bfloat1622float2(*(__nv_bfloat162*)&u);
}

// ---------------- prep: weights fp32->bf16 AND fragment-major bias table ----------------
__global__ void __launch_bounds__(256) prep_kernel(
        const float* __restrict__ s0, const float* __restrict__ s1,
        const float* __restrict__ s2, const float* __restrict__ s3,
        bf16* __restrict__ wb,
        const float* __restrict__ relt, uint4* __restrict__ btabf) {
    int b = blockIdx.x;
    if (b < 192) {                          // weight conversion: 49152 float4
        int i = b * 256 + threadIdx.x;
        const float* s; int off;
        if (i < 12288)      { s = s0; off = 0; }
        else if (i < 16384) { s = s1; off = 12288; }
        else if (i < 32768) { s = s2; off = 16384; }
        else                { s = s3; off = 32768; }
        float4 v = ((const float4*)s)[i - off];
        ((uint2*)wb)[i] = make_uint2(packbf(v.x, v.y), packbf(v.z, v.w));
        return;
    }
    // bias table, fragment-major: [ (wt*4+head)*625 + mt*25+np ][lane] -> uint4
    int gid = (b - 192) * 256 + threadIdx.x;        // 0 .. 640000-1
    int lane = gid & 31;
    int t    = gid >> 5;                            // 0..19999
    int tile = t % 625;
    int hw_  = t / 625;
    int head = hw_ & 3, wt = hw_ >> 2;
    int mt = tile / 25, np = tile % 25;
    int r = lane >> 2, cb = (lane & 3) * 2;
    float vv[2][4];
    #pragma unroll
    for (int ri = 0; ri < 2; ++ri) {
        int row = mt * 16 + r + ri * 8;
        bool rowpad = row >= NTOK;
        int tn = 0, hn = 0, wn_ = 0, regn = 0;
        if (!rowpad) {
            tn = row / 49; hn = (row / 7) % 7; wn_ = row % 7;
            regn = ((wt & 4) ? (tn  < 4 ? 1 : 2) : 0) * 9
                 + ((wt & 2) ? (hn  < 4 ? 1 : 2) : 0) * 3
                 + ((wt & 1) ? (wn_ < 4 ? 1 : 2) : 0);
        }
        #pragma unroll
        for (int ci = 0; ci < 4; ++ci) {
            int col = np * 16 + cb + (ci & 1) + (ci >> 1) * 8;
            float v;
            if (col >= NTOK)      v = -100.f;
            else if (rowpad)      v = 0.f;
            else {
                int tm = col / 49, hm = (col / 7) % 7, wm_ = col % 7;
                int regm = ((wt & 4) ? (tm  < 4 ? 1 : 2) : 0) * 9
                         + ((wt & 2) ? (hm  < 4 ? 1 : 2) : 0) * 3
                         + ((wt & 1) ? (wm_ < 4 ? 1 : 2) : 0);
                int idx = (tn - tm + 7) * 169 + (hn - hm + 6) * 13 + (wn_ - wm_ + 6);
                float bb = relt[idx * NHEAD + head];
                v = (regn == regm) ? bb : bb - 100.f;
            }
            vv[ri][ci] = v;
        }
    }
    uint4 o;
    o.x = packbf(vv[0][0], vv[0][1]);   // fA0: row r,   cols c,c+1
    o.y = packbf(vv[1][0], vv[1][1]);   // fA1: row r+8, cols c,c+1
    o.z = packbf(vv[0][2], vv[0][3]);   // fB0: row r,   cols c+8,c+9
    o.w = packbf(vv[1][2], vv[1][3]);   // fB1: row r+8, cols c+8,c+9
    btabf[(size_t)t * 32 + lane] = o;
}

// ---------------- LN1 (+shift/window-partition), bf16 out ----------------
__global__ void __launch_bounds__(256) ln_kernel(const float* __restrict__ x,
                                                 const float* __restrict__ gw,
                                                 const float* __restrict__ gb,
                                                 bf16* __restrict__ out) {
    int row  = blockIdx.x * 8 + (threadIdx.x >> 5);
    int lane = threadIdx.x & 31;
    int w = row / NTOK, n = row % NTOK;
    int dblk = w >> 6, hblk = (w >> 3) & 7, wblk = w & 7;
    int t = n / 49, hh = (n / 7) % 7, ww = n % 7;
    int gd = (dblk * 8 + t + 4) & 15;
    int gh = hblk * 7 + hh + 3; if (gh >= 56) gh -= 56;
    int gx = wblk * 7 + ww + 3; if (gx >= 56) gx -= 56;
    int src = (gd * 56 + gh) * 56 + gx;
    float4 v = *(const float4*)(x + (size_t)src * CC + lane * 4);
    float s  = v.x + v.y + v.z + v.w;
    float ss = v.x*v.x + v.y*v.y + v.z*v.z + v.w*v.w;
    #pragma unroll
    for (int o = 16; o; o >>= 1) {
        s  += __shfl_xor_sync(~0u, s,  o);
        ss += __shfl_xor_sync(~0u, ss, o);
    }
    float mu  = s * (1.f / CC);
    float var = ss * (1.f / CC) - mu * mu;
    float rs  = rsqrtf(var + 1e-5f);
    float4 gwv = *(const float4*)(gw + lane * 4);
    float4 gbv = *(const float4*)(gb + lane * 4);
    *(uint2*)(out + (size_t)row * CC + lane * 4) = make_uint2(
        packbf((v.x - mu) * rs * gwv.x + gbv.x, (v.y - mu) * rs * gwv.y + gbv.y),
        packbf((v.z - mu) * rs * gwv.z + gbv.z, (v.w - mu) * rs * gwv.w + gbv.w));
}

// ---------------- bf16 HMMA GEMM: 128x128 CTA, 4 warps @ 64x64 ----------------
// EPI: 0=QKV scatter  1=proj+reverse+residual+LN2(fused)  2=FC1+GELU  3=FC2+residual
template<int EPI, int ND, int KK>
__global__ void __launch_bounds__(128) mgemm2(const bf16* __restrict__ A,
                                              const bf16* __restrict__ B,
                                              const float* __restrict__ bias,
                                              const float* __restrict__ extra,
                                              const float* __restrict__ lnw,
                                              const float* __restrict__ lnb,
                                              void* __restrict__ out2,
                                              void* __restrict__ outv) {
    extern __shared__ char smc[];
    const uint32_t smb = (uint32_t)__cvta_generic_to_shared(smc);
    const int tid = threadIdx.x, lane = tid & 31, warp = tid >> 5;
    const int wm = warp >> 1, wn = warp & 1;          // 2x2 warp grid, 64x64 tiles
    const int m0 = blockIdx.x * 128, n0 = blockIdx.y * 128;
    constexpr int NCHUNK = KK / 64;

    float c[4][8][4];
    #pragma unroll
    for (int a = 0; a < 4; ++a)
        #pragma unroll
        for (int b = 0; b < 8; ++b)
            #pragma unroll
            for (int e = 0; e < 4; ++e) c[a][b][e] = 0.f;

    auto load = [&](int ch, int st) {
        uint32_t ab = smb + st * 32768, bb = ab + 16384;
        const char* Ap = (const char*)(A + (size_t)m0 * KK + ch * 64);
        const char* Bp = (const char*)(B + (size_t)n0 * KK + ch * 64);
        #pragma unroll
        for (int i = 0; i < 8; ++i) {
            int cid = tid + i * 128;
            int row = cid >> 3, kb = (cid & 7) * 16;
            cp16(ab + swz(row, kb), Ap + (size_t)row * (KK * 2) + kb);
            cp16(bb + swz(row, kb), Bp + (size_t)row * (KK * 2) + kb);
        }
        asm volatile("cp.async.commit_group;\n");
    };

    load(0, 0);
    if (NCHUNK > 1) load(1, 1);
    asm volatile("cp.async.wait_group %0;\n" :: "n"(1));
    if (NCHUNK == 1) asm volatile("cp.async.wait_group 0;\n");
    __syncthreads();

    #pragma unroll 1
    for (int ch = 0; ch < NCHUNK; ++ch) {
        const int st = ch & 1;
        const uint32_t ab = smb + st * 32768, bb = ab + 16384;
        uint32_t af[2][4][4], bfr[2][4][4];
        auto ldf = [&](int ks, int u) {
            #pragma unroll
            for (int mi = 0; mi < 4; ++mi) {
                int row = wm * 64 + mi * 16 + (lane & 15);
                int kb  = ks * 32 + ((lane & 16) ? 16 : 0);
                LDSM4(af[u][mi], ab + swz(row, kb));
            }
            #pragma unroll
            for (int p = 0; p < 4; ++p) {
                int row = wn * 64 + p * 16 + (lane & 7) + ((lane & 16) ? 8 : 0);
                int kb  = ks * 32 + ((lane & 8) ? 16 : 0);
                LDSM4(bfr[u][p], bb + swz(row, kb));
            }
        };
        ldf(0, 0);
        #pragma unroll
        for (int ks = 0; ks < 4; ++ks) {
            if (ks < 3) ldf(ks + 1, (ks + 1) & 1);
            const int u = ks & 1;
            #pragma unroll
            for (int mi = 0; mi < 4; ++mi)
                #pragma unroll
                for (int p = 0; p < 4; ++p) {
                    MMA16816(c[mi][p*2],   af[u][mi][0], af[u][mi][1], af[u][mi][2], af[u][mi][3],
                             bfr[u][p][0], bfr[u][p][1]);
                    MMA16816(c[mi][p*2+1], af[u][mi][0], af[u][mi][1], af[u][mi][2], af[u][mi][3],
                             bfr[u][p][2], bfr[u][p][3]);
                }
        }
        __syncthreads();
        if (ch + 2 < NCHUNK) load(ch + 2, st);
        if (ch + 1 < NCHUNK) {
            if (ch + 2 < NCHUNK) asm volatile("cp.async.wait_group %0;\n" :: "n"(1));
            else                 asm volatile("cp.async.wait_group 0;\n");
            __syncthreads();
        }
    }

    // ---------------- epilogue ----------------
    const int colb = n0 + wn * 64 + (lane & 3) * 2;
    if (EPI == 1) {
        // proj + window-reverse + shift + residual -> x1 (fp32), then fused LN2 -> m1 (bf16)
        float* redS  = (float*)smc;                 // [2][128]
        float* redSS = redS + 256;
        __syncthreads();                            // smem reuse barrier
        int lins[4][2];
        #pragma unroll
        for (int mi = 0; mi < 4; ++mi) {
            #pragma unroll
            for (int h = 0; h < 2; ++h) {
                int m = m0 + wm * 64 + mi * 16 + (lane >> 2) + h * 8;
                int w = m / NTOK, n = m % NTOK;
                int dblk = w >> 6, hblk = (w >> 3) & 7, wblk = w & 7;
                int t = n / 49, hh = (n / 7) % 7, ww = n % 7;
                int gd = (dblk * 8 + t + 4) & 15;
                int gh = hblk * 7 + hh + 3; if (gh >= 56) gh -= 56;
                int gx = wblk * 7 + ww + 3; if (gx >= 56) gx -= 56;
                int lin = ((gd * 56 + gh) * 56 + gx) * CC;
                lins[mi][h] = lin;
                float s = 0.f, ss = 0.f;
                #pragma unroll
                for (int ni = 0; ni < 8; ++ni) {
                    int j = colb + ni * 8;
                    float2 e = *(const float2*)(extra + lin + j);
                    float v0 = c[mi][ni][h*2+0] + bias[j]   + e.x;
                    float v1 = c[mi][ni][h*2+1] + bias[j+1] + e.y;
                    *(float2*)((float*)outv + lin + j) = make_float2(v0, v1);
                    c[mi][ni][h*2+0] = v0; c[mi][ni][h*2+1] = v1;
                    s  += v0 + v1;
                    ss += v0 * v0 + v1 * v1;
                }
                s  += __shfl_xor_sync(~0u, s, 1);  s  += __shfl_xor_sync(~0u, s, 2);
                ss += __shfl_xor_sync(~0u, ss, 1); ss += __shfl_xor_sync(~0u, ss, 2);
                if ((lane & 3) == 0) {
                    int rrow = wm * 64 + mi * 16 + (lane >> 2) + h * 8;
                    redS [wn * 128 + rrow] = s;
                    redSS[wn * 128 + rrow] = ss;
                }
            }
        }
        __syncthreads();
        bf16* o2 = (bf16*)out2;
        #pragma unroll
        for (int mi = 0; mi < 4; ++mi) {
            #pragma unroll
            for (int h = 0; h < 2; ++h) {
                int rrow = wm * 64 + mi * 16 + (lane >> 2) + h * 8;
                int lin = lins[mi][h];
                float S  = redS[rrow]  + redS[128 + rrow];
                float SS = redSS[rrow] + redSS[128 + rrow];
                float mu  = S * (1.f / CC);
                float var = SS * (1.f / CC) - mu * mu;
                float rs  = rsqrtf(var + 1e-5f);
                #pragma unroll
                for (int ni = 0; ni < 8; ++ni) {
                    int j = colb + ni * 8;
                    float2 gwv = *(const float2*)(lnw + j);
                    float2 gbv = *(const float2*)(lnb + j);
                    float v0 = (c[mi][ni][h*2+0] - mu) * rs * gwv.x + gbv.x;
                    float v1 = (c[mi][ni][h*2+1] - mu) * rs * gwv.y + gbv.y;
                    *(uint32_t*)(o2 + lin + j) = packbf(v0, v1);
                }
            }
        }
        return;
    }
    #pragma unroll
    for (int mi = 0; mi < 4; ++mi) {
        #pragma unroll
        for (int h = 0; h < 2; ++h) {
            int m = m0 + wm * 64 + mi * 16 + (lane >> 2) + h * 8;
            if (EPI == 0) {                 // QKV scatter (+scale q) -> bf16
                int w = m / NTOK, n = m % NTOK;
                bf16* out = (bf16*)outv;
                #pragma unroll
                for (int ni = 0; ni < 8; ++ni) {
                    int j = colb + ni * 8;
                    float v0 = c[mi][ni][h*2+0] + bias[j];
                    float v1 = c[mi][ni][h*2+1] + bias[j+1];
                    int sel = j >> 7, hd = (j >> 5) & 3, dch = j & 31;
                    if (sel == 0) { v0 *= SCALE_Q; v1 *= SCALE_Q; }
                    *(uint32_t*)(out + (size_t)(((sel*NWIN + w)*NHEAD + hd)*NTOK + n)*HEADD + dch)
                        = packbf(v0, v1);
                }
            } else if (EPI == 2) {          // FC1 + exact GELU -> bf16
                bf16* out = (bf16*)outv;
                #pragma unroll
                for (int ni = 0; ni < 8; ++ni) {
                    int j = colb + ni * 8;
                    float v0 = c[mi][ni][h*2+0] + bias[j];
                    float v1 = c[mi][ni][h*2+1] + bias[j+1];
                    v0 = 0.5f * v0 * (1.f + erff(v0 * 0.70710678118654752f));
                    v1 = 0.5f * v1 * (1.f + erff(v1 * 0.70710678118654752f));
                    *(uint32_t*)(out + (size_t)m * HIDD + j) = packbf(v0, v1);
                }
            } else {                        // FC2 + residual -> final fp32 out
                float* out = (float*)outv;
                #pragma unroll
                for (int ni = 0; ni < 8; ++ni) {
                    int j = colb + ni * 8;
                    float2 e = *(const float2*)(extra + (size_t)m * CC + j);
                    *(float2*)(out + (size_t)m * CC + j) = make_float2(
                        c[mi][ni][h*2+0] + bias[j]   + e.x,
                        c[mi][ni][h*2+1] + bias[j+1] + e.y);
                }
            }
        }
    }
}

// ---------------- bf16 tensor-core attention with fragment-major bias ----------------
__global__ void __launch_bounds__(256) attn_mma(const bf16* __restrict__ qkv,
                                                const uint4* __restrict__ btabf,
                                                bf16* __restrict__ y) {
    const int w = blockIdx.x >> 2, head = blockIdx.x & 3;
    extern __shared__ char sm[];
    const uint32_t smb = (uint32_t)__cvta_generic_to_shared(sm);
    const uint32_t ksb = smb, vsb = smb + 32000;

    const int tid = threadIdx.x, lane = tid & 31, warp = tid >> 5;
    const size_t hw = ((size_t)(w * NHEAD + head)) * NTOK * HEADD;
    const bf16* qb = qkv + hw;
    const bf16* kb = qkv + (size_t)MROWS * CC + hw;
    const bf16* vb = qkv + 2 * (size_t)MROWS * CC + hw;

    for (int i = tid; i < 320; i += 256) {
        int buf = (i >= 160);
        int j = i - buf * 160;
        *(uint32_t*)(sm + buf * 32000 + 392 * 80 + j * 4) = 0u;
    }
    for (int i = tid; i < NTOK * 4; i += 256) {
        int row = i >> 2, off = i & 3;
        cp16(ksb + row * 80 + off * 16, kb + row * 32 + off * 8);
        cp16(vsb + row * 80 + off * 16, vb + row * 32 + off * 8);
    }
    asm volatile("cp.async.commit_group;\n");
    asm volatile("cp.async.wait_group 0;\n");
    __syncthreads();

    const int wtype = ((w >> 6) << 2) | ((((w >> 3) & 7) == 7) ? 2 : 0) | (((w & 7) == 7) ? 1 : 0);
    const uint4* btb = btabf + (size_t)((wtype * NHEAD + head) * 625) * 32 + lane;

    const int r  = lane >> 2, c2 = (lane & 3) * 2;
    const int lrow = (lane & 7) + ((lane & 16) ? 8 : 0);
    const int loff = (lane & 8) ? 16 : 0;

    for (int mt = warp; mt < 25; mt += 8) {
        const int m0r = mt * 16;
        uint32_t qa[2][4];
        #pragma unroll
        for (int kt = 0; kt < 2; ++kt) {
            qa[kt][0] = *(const uint32_t*)(qb + (m0r + r    ) * 32 + kt * 16 +     c2);
            qa[kt][1] = *(const uint32_t*)(qb + (m0r + r + 8) * 32 + kt * 16 +     c2);
            qa[kt][2] = *(const uint32_t*)(qb + (m0r + r    ) * 32 + kt * 16 + 8 + c2);
            qa[kt][3] = *(const uint32_t*)(qb + (m0r + r + 8) * 32 + kt * 16 + 8 + c2);
        }
        float oc[4][4];
        #pragma unroll
        for (int a = 0; a < 4; ++a)
            #pragma unroll
            for (int e = 0; e < 4; ++e) oc[a][e] = 0.f;
        float rs0 = 0.f, rs1 = 0.f;
        const uint4* btile = btb + (size_t)(mt * 25) * 32;

        for (int np = 0; np < 25; ++np) {
            uint4 bv = btile[(size_t)np * 32];       // ONE coalesced 16B load
            uint32_t kadr = ksb + (np * 16 + lrow) * 80 + loff;
            uint32_t kf0[4], kf1[4];
            LDSM4(kf0, kadr);
            LDSM4(kf1, kadr + 32);
            float sA[4] = {0.f, 0.f, 0.f, 0.f};
            float sB[4] = {0.f, 0.f, 0.f, 0.f};
            MMA16816(sA, qa[0][0], qa[0][1], qa[0][2], qa[0][3], kf0[0], kf0[1]);
            MMA16816(sA, qa[1][0], qa[1][1], qa[1][2], qa[1][3], kf1[0], kf1[1]);
            MMA16816(sB, qa[0][0], qa[0][1], qa[0][2], qa[0][3], kf0[2], kf0[3]);
            MMA16816(sB, qa[1][0], qa[1][1], qa[1][2], qa[1][3], kf1[2], kf1[3]);
            float2 fA0 = unpackbf(bv.x);
            float2 fA1 = unpackbf(bv.y);
            float2 fB0 = unpackbf(bv.z);
            float2 fB1 = unpackbf(bv.w);
            float e0 = __expf(sA[0] + fA0.x), e1 = __expf(sA[1] + fA0.y);
            float e2 = __expf(sA[2] + fA1.x), e3 = __expf(sA[3] + fA1.y);
            float e4 = __expf(sB[0] + fB0.x), e5 = __expf(sB[1] + fB0.y);
            float e6 = __expf(sB[2] + fB1.x), e7 = __expf(sB[3] + fB1.y);
            rs0 += e0 + e1 + e4 + e5;
            rs1 += e2 + e3 + e6 + e7;
            uint32_t pa0 = packbf(e0, e1), pa1 = packbf(e2, e3);
            uint32_t pa2 = packbf(e4, e5), pa3 = packbf(e6, e7);
            uint32_t vadr = vsb + (np * 16 + lrow) * 80 + loff;
            uint32_t vf0[4], vf1[4];
            LDSM4T(vf0, vadr);
            LDSM4T(vf1, vadr + 32);
            MMA16816(oc[0], pa0, pa1, pa2, pa3, vf0[0], vf0[2]);
            MMA16816(oc[1], pa0, pa1, pa2, pa3, vf0[1], vf0[3]);
            MMA16816(oc[2], pa0, pa1, pa2, pa3, vf1[0], vf1[2]);
            MMA16816(oc[3], pa0, pa1, pa2, pa3, vf1[1], vf1[3]);
        }
        rs0 += __shfl_xor_sync(~0u, rs0, 1); rs0 += __shfl_xor_sync(~0u, rs0, 2);
        rs1 += __shfl_xor_sync(~0u, rs1, 1); rs1 += __shfl_xor_sync(~0u, rs1, 2);
        float i0 = 1.f / rs0, i1 = 1.f / rs1;
        {
            size_t yb = ((size_t)(w * NTOK + m0r + r)) * CC + head * HEADD + c2;
            #pragma unroll
            for (int dt = 0; dt < 4; ++dt)
                *(uint32_t*)(y + yb + dt * 8) = packbf(oc[dt][0] * i0, oc[dt][1] * i0);
        }
        if (m0r + r + 8 < NTOK) {
            size_t yb = ((size_t)(w * NTOK + m0r + r + 8)) * CC + head * HEADD + c2;
            #pragma unroll
            for (int dt = 0; dt < 4; ++dt)
                *(uint32_t*)(y + yb + dt * 8) = packbf(oc[dt][2] * i1, oc[dt][3] * i1);
        }
    }
}

// ---------------- launch ----------------
extern "C" void kernel_launch(void* const* d_in, const int* in_sizes, int n_in,
                              void* d_out, int out_size) {
    (void)in_sizes; (void)n_in; (void)out_size;
    const float* x     = (const float*)d_in[0];
    const float* n1w   = (const float*)d_in[1];
    const float* n1b   = (const float*)d_in[2];
    const float* qkvw  = (const float*)d_in[3];
    const float* qkvb  = (const float*)d_in[4];
    const float* relt  = (const float*)d_in[5];
    const float* projw = (const float*)d_in[6];
    const float* projb = (const float*)d_in[7];
    const float* n2w   = (const float*)d_in[8];
    const float* n2b   = (const float*)d_in[9];
    const float* fc1w  = (const float*)d_in[10];
    const float* fc1b  = (const float*)d_in[11];
    const float* fc2w  = (const float*)d_in[12];
    const float* fc2b  = (const float*)d_in[13];

    bf16 *win, *qkvB, *yB, *m1, *hid, *wb;
    float *x1;
    uint4 *btabf;
    cudaGetSymbolAddress((void**)&win,   g_win);
    cudaGetSymbolAddress((void**)&qkvB,  g_qkv);
    cudaGetSymbolAddress((void**)&yB,    g_y);
    cudaGetSymbolAddress((void**)&x1,    g_x1);
    cudaGetSymbolAddress((void**)&m1,    g_m1);
    cudaGetSymbolAddress((void**)&hid,   g_hid);
    cudaGetSymbolAddress((void**)&wb,    g_wb);
    cudaGetSymbolAddress((void**)&btabf, g_btabf);

    cudaFuncSetAttribute(attn_mma, cudaFuncAttributeMaxDynamicSharedMemorySize, SMEM_ATT);
    cudaFuncSetAttribute(mgemm2<0,384,128>, cudaFuncAttributeMaxDynamicSharedMemorySize, SMEM_G2);
    cudaFuncSetAttribute(mgemm2<1,128,128>, cudaFuncAttributeMaxDynamicSharedMemorySize, SMEM_G2);
    cudaFuncSetAttribute(mgemm2<2,512,128>, cudaFuncAttributeMaxDynamicSharedMemorySize, SMEM_G2);
    cudaFuncSetAttribute(mgemm2<3,128,512>, cudaFuncAttributeMaxDynamicSharedMemorySize, SMEM_G2);

    prep_kernel<<<192 + 2500, 256>>>(qkvw, projw, fc1w, fc2w, wb, relt, btabf);
    ln_kernel<<<MROWS / 8, 256>>>(x, n1w, n1b, win);
    mgemm2<0, 384, 128><<<dim3(392, 3), 128, SMEM_G2>>>(win, wb, qkvb,
        nullptr, nullptr, nullptr, nullptr, qkvB);
    attn_mma<<<NWIN * NHEAD, 256, SMEM_ATT>>>(qkvB, btabf, yB);
    mgemm2<1, 128, 128><<<dim3(392, 1), 128, SMEM_G2>>>(yB, wb + 49152, projb,
        x, n2w, n2b, m1, x1);
    mgemm2<2, 512, 128><<<dim3(392, 4), 128, SMEM_G2>>>(m1, wb + 65536, fc1b,
        nullptr, nullptr, nullptr, nullptr, hid);
    mgemm2<3, 128, 512><<<dim3(392, 1), 128, SMEM_G2>>>(hid, wb + 131072, fc2b,
        x1, nullptr, nullptr, nullptr, (float*)d_out);
}